// round 13
// baseline (speedup 1.0000x reference)
#include <cuda_runtime.h>
#include <math.h>

#define Bb 256
#define Tt 256
#define Dd 64
#define Hh 512
#define NCT 32                     // cols per CTA tile

typedef unsigned long long ull;

// Scratch (device globals: allocation-free rule).
__device__ float g_xp[(size_t)Bb * Tt * Hh];   // xp buffer A
__device__ float g_xq[(size_t)Bb * Tt * Hh];   // xp buffer B
__device__ float g_hx[2 * Bb * Hh];            // 1MB L2-hot h exchange (double)
__device__ int   g_bar[3 * 8];                 // per (layer, group-of-32) counters

// ---------------- packed dual-fp32 helpers (sm_100+ f32x2) ----------------
__device__ __forceinline__ ull fma2(ull a, ull b, ull c) {
    ull d;
    asm("fma.rn.f32x2 %0, %1, %2, %3;" : "=l"(d) : "l"(a), "l"(b), "l"(c));
    return d;
}
__device__ __forceinline__ ull dup2(float x) {
    ull d;
    asm("mov.b64 %0, {%1, %2};" : "=l"(d) : "f"(x), "f"(x));
    return d;
}
__device__ __forceinline__ ull pack2(float x, float y) {
    ull d;
    asm("mov.b64 %0, {%1, %2};" : "=l"(d) : "f"(x), "f"(y));
    return d;
}
__device__ __forceinline__ float2 unpack2(ull v) {
    float2 r;
    asm("mov.b64 {%0, %1}, %2;" : "=f"(r.x), "=f"(r.y) : "l"(v));
    return r;
}
__device__ __forceinline__ int ld_acquire(const int* p) {
    int v;
    asm volatile("ld.acquire.gpu.global.b32 %0, [%1];" : "=r"(v) : "l"(p));
    return v;
}
__device__ __forceinline__ void red_release_add(int* p, int v) {
    asm volatile("red.release.gpu.global.add.s32 [%0], %1;" :: "l"(p), "r"(v) : "memory");
}
__device__ __forceinline__ void red_add_f32(float* p, float v) {
    asm volatile("red.global.add.f32 [%0], %1;" :: "l"(p), "f"(v) : "memory");
}
__device__ __forceinline__ float fast_tanh(float x) {
    float ax = fabsf(x);
    float e;
    asm("ex2.approx.f32 %0, %1;" : "=f"(e) : "f"(ax * 2.885390082f));
    float t = 1.0f - __fdividef(2.0f, e + 1.0f);
    return copysignf(t, x);
}

__global__ void zero_bar_kernel() {
    if (threadIdx.x < 24) g_bar[threadIdx.x] = 0;
}

// ---------------------------------------------------------------------------
// Projection GEMM for layer 0 only: out[M,Hh] = A[M,64] @ W[64,Hh] + bias
// ---------------------------------------------------------------------------
template <int K>
__global__ __launch_bounds__(256) void proj_kernel(
    const float* __restrict__ A, const float* __restrict__ W,
    const float* __restrict__ bias, float* __restrict__ out)
{
    __shared__ float sA[16 * 132];
    __shared__ float sB[16 * 128];

    const int n0 = blockIdx.x * 128;
    const int m0 = blockIdx.y * 128;
    const int tid = threadIdx.x;
    const int tx = tid & 15;
    const int ty = tid >> 4;

    const int arow = tid >> 1;
    const int ak   = (tid & 1) * 8;
    const int bk   = tid >> 4;
    const int bc   = (tid & 15) * 8;

    ull acc[8][4];
#pragma unroll
    for (int i = 0; i < 8; i++)
#pragma unroll
        for (int j = 0; j < 4; j++) acc[i][j] = 0ull;

    float4 va0 = *(const float4*)&A[(size_t)(m0 + arow) * K + ak];
    float4 va1 = *(const float4*)&A[(size_t)(m0 + arow) * K + ak + 4];
    float4 vb0 = *(const float4*)&W[(size_t)bk * Hh + n0 + bc];
    float4 vb1 = *(const float4*)&W[(size_t)bk * Hh + n0 + bc + 4];

    const int NB = K / 16;
    for (int kb = 0; kb < NB; kb++) {
        sA[(ak + 0) * 132 + arow] = va0.x;
        sA[(ak + 1) * 132 + arow] = va0.y;
        sA[(ak + 2) * 132 + arow] = va0.z;
        sA[(ak + 3) * 132 + arow] = va0.w;
        sA[(ak + 4) * 132 + arow] = va1.x;
        sA[(ak + 5) * 132 + arow] = va1.y;
        sA[(ak + 6) * 132 + arow] = va1.z;
        sA[(ak + 7) * 132 + arow] = va1.w;
        *(float4*)&sB[bk * 128 + bc]     = vb0;
        *(float4*)&sB[bk * 128 + bc + 4] = vb1;
        __syncthreads();

        if (kb + 1 < NB) {
            int k0 = (kb + 1) * 16;
            va0 = *(const float4*)&A[(size_t)(m0 + arow) * K + k0 + ak];
            va1 = *(const float4*)&A[(size_t)(m0 + arow) * K + k0 + ak + 4];
            vb0 = *(const float4*)&W[(size_t)(k0 + bk) * Hh + n0 + bc];
            vb1 = *(const float4*)&W[(size_t)(k0 + bk) * Hh + n0 + bc + 4];
        }

#pragma unroll
        for (int kk = 0; kk < 16; kk++) {
            float4 a0 = *(const float4*)&sA[kk * 132 + ty * 8];
            float4 a1 = *(const float4*)&sA[kk * 132 + ty * 8 + 4];
            ulonglong2 b0 = *(const ulonglong2*)&sB[kk * 128 + tx * 8];
            ulonglong2 b1 = *(const ulonglong2*)&sB[kk * 128 + tx * 8 + 4];
            float ar[8] = {a0.x, a0.y, a0.z, a0.w, a1.x, a1.y, a1.z, a1.w};
#pragma unroll
            for (int r = 0; r < 8; r++) {
                ull av = dup2(ar[r]);
                acc[r][0] = fma2(av, b0.x, acc[r][0]);
                acc[r][1] = fma2(av, b0.y, acc[r][1]);
                acc[r][2] = fma2(av, b1.x, acc[r][2]);
                acc[r][3] = fma2(av, b1.y, acc[r][3]);
            }
        }
        __syncthreads();
    }

    float4 bi0 = *(const float4*)&bias[n0 + tx * 8];
    float4 bi1 = *(const float4*)&bias[n0 + tx * 8 + 4];
#pragma unroll
    for (int r = 0; r < 8; r++) {
        float2 u0 = unpack2(acc[r][0]);
        float2 u1 = unpack2(acc[r][1]);
        float2 u2 = unpack2(acc[r][2]);
        float2 u3 = unpack2(acc[r][3]);
        float4 o0, o1;
        o0.x = u0.x + bi0.x; o0.y = u0.y + bi0.y; o0.z = u1.x + bi0.z; o0.w = u1.y + bi0.w;
        o1.x = u2.x + bi1.x; o1.y = u2.y + bi1.y; o1.z = u3.x + bi1.z; o1.w = u3.y + bi1.w;
        size_t base = (size_t)(m0 + ty * 8 + r) * Hh + n0 + tx * 8;
        *(float4*)&out[base]     = o0;
        *(float4*)&out[base + 4] = o1;
    }
}

// ---------------------------------------------------------------------------
// Fused persistent layer kernel (R12 structure; filler epilogue replaced by
// direct L2 red.add into xpo — bias folded into kc==0 accumulator init).
// Grid (16 col-tiles of 32 x 8 groups of 32 rows) = 128 CTAs, 256 threads.
// ---------------------------------------------------------------------------
#define SH_STR  514
#define RED_STR 34
#define SWH_F   (512 * NCT)             // 16384 floats
#define SH_F    (32 * SH_STR)           // 16448
#define RED_F   (4 * 32 * RED_STR)      // 4352
#define LAYER_SMEM ((2 * SWH_F + SH_F + RED_F) * 4)   // 214272 B

extern __shared__ float s_mem[];

__global__ __launch_bounds__(256, 1) void layer_kernel(
    const float* __restrict__ xp,  const float* __restrict__ Wh,
    const float* __restrict__ Wx,  const float* __restrict__ bnext,
    float* __restrict__ xpo,       float* __restrict__ hx,
    int* __restrict__ bar, int layer)
{
    float* sWh  = s_mem;                       // [512][32]
    float* sWx  = s_mem + SWH_F;               // [512][32]
    float* sH   = s_mem + 2 * SWH_F;           // [32][514]
    float* sRed = s_mem + 2 * SWH_F + SH_F;    // [4][32][34]

    const int n0 = blockIdx.x * NCT;
    const int b0 = blockIdx.y * 32;
    int* cnt = &bar[layer * 8 + blockIdx.y];

    const int tid  = threadIdx.x;
    const int w    = tid >> 5;
    const int lane = tid & 31;
    const int kc   = w >> 1;             // k-chunk 0..3 (128 k each)
    const int rh   = w & 1;              // row half (16 rows)
    const int rg   = lane >> 3;          // row group of 4 within half
    const int cg   = lane & 7;           // 8 col groups of 4
    const int kbase = kc * 128;
    const int rbase = rh * 16 + rg * 4;

    const int er = tid >> 3;             // epilogue row 0..31
    const int ec = (tid & 7) * 4;        // epilogue col group

    // ---- stage Wh (and Wx_next) column slices once ----
    for (int i = tid; i < 512 * 8; i += 256) {     // 4096 float4 slots
        int k = i >> 3, c4 = i & 7;
        float4 v = *(const float4*)&Wh[(size_t)k * Hh + n0 + c4 * 4];
        *(float4*)&sWh[k * NCT + c4 * 4] = v;
    }
    if (Wx) {
        for (int i = tid; i < 512 * 8; i += 256) {
            int k = i >> 3, c4 = i & 7;
            float4 v = *(const float4*)&Wx[(size_t)k * Hh + n0 + c4 * 4];
            *(float4*)&sWx[k * NCT + c4 * 4] = v;
        }
    }
    // filler bias (lane indexing): bias init for kc==0 accumulators
    ull bL = 0ull, bH = 0ull;
    if (Wx && kc == 0) {
        float4 bw = *(const float4*)&bnext[n0 + cg * 4];
        bL = pack2(bw.x, bw.y);
        bH = pack2(bw.z, bw.w);
    }

    // ---- t = 0: h0 = tanh(xp0) -> hx[0] ----
    {
        size_t base = ((size_t)(b0 + er) * Tt) * Hh + n0 + ec;
        float4 xv = *(const float4*)&xp[base];
        float4 o;
        o.x = fast_tanh(xv.x); o.y = fast_tanh(xv.y);
        o.z = fast_tanh(xv.z); o.w = fast_tanh(xv.w);
        __stcg((float4*)&hx[(size_t)(b0 + er) * Hh + n0 + ec], o);
    }
    __syncthreads();                 // weights staged + h0 issued
    if (tid == 0) red_release_add(cnt, 1);

    for (int t = 1; t < Tt; t++) {
        // prefetch xp for this step (independent of the flag)
        size_t obase = (((size_t)(b0 + er) * Tt) + t) * Hh + n0 + ec;
        float4 xv = *(const float4*)&xp[obase];

        // ---- wait for all 16 producers of h_{t-1} ----
        if (tid == 0) {
            while (ld_acquire(cnt) < 16 * t) { }
        }
        __syncthreads();

        // ---- stage h_{t-1}[b0..b0+31, :] from hx ----
        {
            const float* src = hx + ((size_t)((t - 1) & 1)) * (Bb * Hh);
#pragma unroll
            for (int half = 0; half < 2; half++) {
                float4 sv[8];
#pragma unroll
                for (int j = 0; j < 8; j++) {
                    int slot = tid + (half * 8 + j) * 256;
                    int row = slot >> 7, k4 = slot & 127;
                    sv[j] = __ldcg((const float4*)&src[(size_t)(b0 + row) * Hh + k4 * 4]);
                }
#pragma unroll
                for (int j = 0; j < 8; j++) {
                    int slot = tid + (half * 8 + j) * 256;
                    int row = slot >> 7, k4 = slot & 127;
                    float* d = &sH[row * SH_STR + k4 * 4];
                    *(float2*)&d[0] = make_float2(sv[j].x, sv[j].y);
                    *(float2*)&d[2] = make_float2(sv[j].z, sv[j].w);
                }
            }
        }
        __syncthreads();

        // ---- recurrence compute: warp (kc, rh): [16 rows x 32 cols], 128 k ----
        {
            ull a00 = 0, a01 = 0, a10 = 0, a11 = 0,
                a20 = 0, a21 = 0, a30 = 0, a31 = 0;
            const float* hp = &sH[rbase * SH_STR + kbase];
            const float* wp = &sWh[kbase * NCT];
#pragma unroll 8
            for (int kk = 0; kk < 128; kk += 2) {
                float2 h0 = *(const float2*)&hp[kk];
                float2 h1 = *(const float2*)&hp[SH_STR + kk];
                float2 h2 = *(const float2*)&hp[2 * SH_STR + kk];
                float2 h3 = *(const float2*)&hp[3 * SH_STR + kk];
                ulonglong2 wa = *(const ulonglong2*)&wp[kk * NCT + cg * 4];
                ulonglong2 wb = *(const ulonglong2*)&wp[(kk + 1) * NCT + cg * 4];
                ull a;
                a = dup2(h0.x); a00 = fma2(a, wa.x, a00); a01 = fma2(a, wa.y, a01);
                a = dup2(h1.x); a10 = fma2(a, wa.x, a10); a11 = fma2(a, wa.y, a11);
                a = dup2(h2.x); a20 = fma2(a, wa.x, a20); a21 = fma2(a, wa.y, a21);
                a = dup2(h3.x); a30 = fma2(a, wa.x, a30); a31 = fma2(a, wa.y, a31);
                a = dup2(h0.y); a00 = fma2(a, wb.x, a00); a01 = fma2(a, wb.y, a01);
                a = dup2(h1.y); a10 = fma2(a, wb.x, a10); a11 = fma2(a, wb.y, a11);
                a = dup2(h2.y); a20 = fma2(a, wb.x, a20); a21 = fma2(a, wb.y, a21);
                a = dup2(h3.y); a30 = fma2(a, wb.x, a30); a31 = fma2(a, wb.y, a31);
            }
            float* d0 = &sRed[kc * (32 * RED_STR) + (rbase + 0) * RED_STR + cg * 4];
            float* d1 = &sRed[kc * (32 * RED_STR) + (rbase + 1) * RED_STR + cg * 4];
            float* d2 = &sRed[kc * (32 * RED_STR) + (rbase + 2) * RED_STR + cg * 4];
            float* d3 = &sRed[kc * (32 * RED_STR) + (rbase + 3) * RED_STR + cg * 4];
            *(ull*)&d0[0] = a00; *(ull*)&d0[2] = a01;
            *(ull*)&d1[0] = a10; *(ull*)&d1[2] = a11;
            *(ull*)&d2[0] = a20; *(ull*)&d2[2] = a21;
            *(ull*)&d3[0] = a30; *(ull*)&d3[2] = a31;
        }
        __syncthreads();

        // ---- reduce 4 partials, add xp, tanh, store h_t to hx ----
        {
            float2 s0 = make_float2(0.f, 0.f), s1 = make_float2(0.f, 0.f);
            int rb = er * RED_STR + ec;
#pragma unroll
            for (int q = 0; q < 4; q++) {
                float2 u0 = unpack2(*(const ull*)&sRed[q * (32 * RED_STR) + rb]);
                float2 u1 = unpack2(*(const ull*)&sRed[q * (32 * RED_STR) + rb + 2]);
                s0.x += u0.x; s0.y += u0.y; s1.x += u1.x; s1.y += u1.y;
            }
            float4 o;
            o.x = fast_tanh(s0.x + xv.x); o.y = fast_tanh(s0.y + xv.y);
            o.z = fast_tanh(s1.x + xv.z); o.w = fast_tanh(s1.y + xv.w);
            __stcg((float4*)&hx[((size_t)(t & 1)) * (Bb * Hh)
                                + (size_t)(b0 + er) * Hh + n0 + ec], o);
        }
        __syncthreads();                     // sync C: stores issued before release
        if (tid == 0) red_release_add(cnt, 1);

        // ---- FILLER: next layer's projection of h_{t-1}; partial sums go
        //      straight to xpo via L2 red.add (bias in kc==0 init) ----
        if (Wx) {
            ull a00 = bL, a01 = bH, a10 = bL, a11 = bH,
                a20 = bL, a21 = bH, a30 = bL, a31 = bH;
            const float* hp = &sH[rbase * SH_STR + kbase];
            const float* wp = &sWx[kbase * NCT];
#pragma unroll 8
            for (int kk = 0; kk < 128; kk += 2) {
                float2 h0 = *(const float2*)&hp[kk];
                float2 h1 = *(const float2*)&hp[SH_STR + kk];
                float2 h2 = *(const float2*)&hp[2 * SH_STR + kk];
                float2 h3 = *(const float2*)&hp[3 * SH_STR + kk];
                ulonglong2 wa = *(const ulonglong2*)&wp[kk * NCT + cg * 4];
                ulonglong2 wb = *(const ulonglong2*)&wp[(kk + 1) * NCT + cg * 4];
                ull a;
                a = dup2(h0.x); a00 = fma2(a, wa.x, a00); a01 = fma2(a, wa.y, a01);
                a = dup2(h1.x); a10 = fma2(a, wa.x, a10); a11 = fma2(a, wa.y, a11);
                a = dup2(h2.x); a20 = fma2(a, wa.x, a20); a21 = fma2(a, wa.y, a21);
                a = dup2(h3.x); a30 = fma2(a, wa.x, a30); a31 = fma2(a, wa.y, a31);
                a = dup2(h0.y); a00 = fma2(a, wb.x, a00); a01 = fma2(a, wb.y, a01);
                a = dup2(h1.y); a10 = fma2(a, wb.x, a10); a11 = fma2(a, wb.y, a11);
                a = dup2(h2.y); a20 = fma2(a, wb.x, a20); a21 = fma2(a, wb.y, a21);
                a = dup2(h3.y); a30 = fma2(a, wb.x, a30); a31 = fma2(a, wb.y, a31);
            }
            {
                float2 u;
                float* p0 = &xpo[(((size_t)(b0 + rbase + 0) * Tt) + (t - 1)) * Hh + n0 + cg * 4];
                u = unpack2(a00); red_add_f32(p0 + 0, u.x); red_add_f32(p0 + 1, u.y);
                u = unpack2(a01); red_add_f32(p0 + 2, u.x); red_add_f32(p0 + 3, u.y);
                float* p1 = &xpo[(((size_t)(b0 + rbase + 1) * Tt) + (t - 1)) * Hh + n0 + cg * 4];
                u = unpack2(a10); red_add_f32(p1 + 0, u.x); red_add_f32(p1 + 1, u.y);
                u = unpack2(a11); red_add_f32(p1 + 2, u.x); red_add_f32(p1 + 3, u.y);
                float* p2 = &xpo[(((size_t)(b0 + rbase + 2) * Tt) + (t - 1)) * Hh + n0 + cg * 4];
                u = unpack2(a20); red_add_f32(p2 + 0, u.x); red_add_f32(p2 + 1, u.y);
                u = unpack2(a21); red_add_f32(p2 + 2, u.x); red_add_f32(p2 + 3, u.y);
                float* p3 = &xpo[(((size_t)(b0 + rbase + 3) * Tt) + (t - 1)) * Hh + n0 + cg * 4];
                u = unpack2(a30); red_add_f32(p3 + 0, u.x); red_add_f32(p3 + 1, u.y);
                u = unpack2(a31); red_add_f32(p3 + 2, u.x); red_add_f32(p3 + 3, u.y);
            }
            __syncthreads();   // filler sH reads done before next step's dump
        }
    }

    // ---- tail: projection of h_{Tt-1} ----
    if (Wx) {
        if (tid == 0) {
            while (ld_acquire(cnt) < 16 * Tt) { }
        }
        __syncthreads();
        {
            const float* src = hx + ((size_t)((Tt - 1) & 1)) * (Bb * Hh);
#pragma unroll
            for (int half = 0; half < 2; half++) {
                float4 sv[8];
#pragma unroll
                for (int j = 0; j < 8; j++) {
                    int slot = tid + (half * 8 + j) * 256;
                    int row = slot >> 7, k4 = slot & 127;
                    sv[j] = __ldcg((const float4*)&src[(size_t)(b0 + row) * Hh + k4 * 4]);
                }
#pragma unroll
                for (int j = 0; j < 8; j++) {
                    int slot = tid + (half * 8 + j) * 256;
                    int row = slot >> 7, k4 = slot & 127;
                    float* d = &sH[row * SH_STR + k4 * 4];
                    *(float2*)&d[0] = make_float2(sv[j].x, sv[j].y);
                    *(float2*)&d[2] = make_float2(sv[j].z, sv[j].w);
                }
            }
        }
        __syncthreads();
        {
            ull a00 = bL, a01 = bH, a10 = bL, a11 = bH,
                a20 = bL, a21 = bH, a30 = bL, a31 = bH;
            const float* hp = &sH[rbase * SH_STR + kbase];
            const float* wp = &sWx[kbase * NCT];
#pragma unroll 8
            for (int kk = 0; kk < 128; kk += 2) {
                float2 h0 = *(const float2*)&hp[kk];
                float2 h1 = *(const float2*)&hp[SH_STR + kk];
                float2 h2 = *(const float2*)&hp[2 * SH_STR + kk];
                float2 h3 = *(const float2*)&hp[3 * SH_STR + kk];
                ulonglong2 wa = *(const ulonglong2*)&wp[kk * NCT + cg * 4];
                ulonglong2 wb = *(const ulonglong2*)&wp[(kk + 1) * NCT + cg * 4];
                ull a;
                a = dup2(h0.x); a00 = fma2(a, wa.x, a00); a01 = fma2(a, wa.y, a01);
                a = dup2(h1.x); a10 = fma2(a, wa.x, a10); a11 = fma2(a, wa.y, a11);
                a = dup2(h2.x); a20 = fma2(a, wa.x, a20); a21 = fma2(a, wa.y, a21);
                a = dup2(h3.x); a30 = fma2(a, wa.x, a30); a31 = fma2(a, wa.y, a31);
                a = dup2(h0.y); a00 = fma2(a, wb.x, a00); a01 = fma2(a, wb.y, a01);
                a = dup2(h1.y); a10 = fma2(a, wb.x, a10); a11 = fma2(a, wb.y, a11);
                a = dup2(h2.y); a20 = fma2(a, wb.x, a20); a21 = fma2(a, wb.y, a21);
                a = dup2(h3.y); a30 = fma2(a, wb.x, a30); a31 = fma2(a, wb.y, a31);
            }
            float2 u;
            float* p0 = &xpo[(((size_t)(b0 + rbase + 0) * Tt) + (Tt - 1)) * Hh + n0 + cg * 4];
            u = unpack2(a00); red_add_f32(p0 + 0, u.x); red_add_f32(p0 + 1, u.y);
            u = unpack2(a01); red_add_f32(p0 + 2, u.x); red_add_f32(p0 + 3, u.y);
            float* p1 = &xpo[(((size_t)(b0 + rbase + 1) * Tt) + (Tt - 1)) * Hh + n0 + cg * 4];
            u = unpack2(a10); red_add_f32(p1 + 0, u.x); red_add_f32(p1 + 1, u.y);
            u = unpack2(a11); red_add_f32(p1 + 2, u.x); red_add_f32(p1 + 3, u.y);
            float* p2 = &xpo[(((size_t)(b0 + rbase + 2) * Tt) + (Tt - 1)) * Hh + n0 + cg * 4];
            u = unpack2(a20); red_add_f32(p2 + 0, u.x); red_add_f32(p2 + 1, u.y);
            u = unpack2(a21); red_add_f32(p2 + 2, u.x); red_add_f32(p2 + 3, u.y);
            float* p3 = &xpo[(((size_t)(b0 + rbase + 3) * Tt) + (Tt - 1)) * Hh + n0 + cg * 4];
            u = unpack2(a30); red_add_f32(p3 + 0, u.x); red_add_f32(p3 + 1, u.y);
            u = unpack2(a31); red_add_f32(p3 + 2, u.x); red_add_f32(p3 + 3, u.y);
        }
    }
}

// ---------------------------------------------------------------------------
// Final: out[b] = hx[1][b,:] @ Wf + bf   (h at t=255, parity 1)
// ---------------------------------------------------------------------------
__global__ void final_kernel(const float* __restrict__ hx, const float* __restrict__ Wf,
                             const float* __restrict__ bf, float* __restrict__ out)
{
    int b = blockIdx.x;
    const float* row = hx + (size_t)(Bb * Hh) + (size_t)b * Hh;
    float s = 0.f;
    for (int j = threadIdx.x; j < Hh; j += 128) s += row[j] * Wf[j];
#pragma unroll
    for (int o = 16; o > 0; o >>= 1) s += __shfl_down_sync(0xffffffffu, s, o);
    __shared__ float ws[4];
    if ((threadIdx.x & 31) == 0) ws[threadIdx.x >> 5] = s;
    __syncthreads();
    if (threadIdx.x == 0) out[b] = ws[0] + ws[1] + ws[2] + ws[3] + bf[0];
}

// ---------------------------------------------------------------------------
extern "C" void kernel_launch(void* const* d_in, const int* in_sizes, int n_in,
                              void* d_out, int out_size)
{
    const float* x    = (const float*)d_in[0];
    const float* Wx0  = (const float*)d_in[1];
    const float* Wh0  = (const float*)d_in[2];
    const float* bi0  = (const float*)d_in[3];
    const float* Wx1  = (const float*)d_in[4];
    const float* Wh1  = (const float*)d_in[5];
    const float* bi1  = (const float*)d_in[6];
    const float* Wx2  = (const float*)d_in[7];
    const float* Wh2  = (const float*)d_in[8];
    const float* bi2  = (const float*)d_in[9];
    const float* Wf   = (const float*)d_in[10];
    const float* bf   = (const float*)d_in[11];
    float* out = (float*)d_out;

    void* p;
    cudaGetSymbolAddress(&p, g_xp);
    float* xpA = (float*)p;
    cudaGetSymbolAddress(&p, g_xq);
    float* xpB = (float*)p;
    cudaGetSymbolAddress(&p, g_hx);
    float* hx = (float*)p;
    cudaGetSymbolAddress(&p, g_bar);
    int* bar = (int*)p;

    const size_t XP_BYTES = (size_t)Bb * Tt * Hh * sizeof(float);

    cudaFuncSetAttribute(layer_kernel, cudaFuncAttributeMaxDynamicSharedMemorySize, LAYER_SMEM);

    dim3 pgrid(Hh / 128, (Bb * Tt) / 128);   // (4, 512)
    dim3 lgrid(Hh / NCT, Bb / 32);           // (16, 8) = 128 CTAs

    zero_bar_kernel<<<1, 32>>>();

    // zero xpB (layer-0's RED target)
    cudaMemsetAsync(xpB, 0, XP_BYTES, 0);
    // layer 0 input projection (K=64)
    proj_kernel<Dd><<<pgrid, 256>>>(x, Wx0, bi0, xpA);
    // layer 0 recurrence + fused RED-projection for layer 1
    layer_kernel<<<lgrid, 256, LAYER_SMEM>>>(xpA, Wh0, Wx1, bi1, xpB, hx, bar, 0);
    // zero xpA (layer-1's RED target; safe: layer-0 kernel has finished reading it)
    cudaMemsetAsync(xpA, 0, XP_BYTES, 0);
    // layer 1 recurrence + fused RED-projection for layer 2
    layer_kernel<<<lgrid, 256, LAYER_SMEM>>>(xpB, Wh1, Wx2, bi2, xpA, hx, bar, 1);
    // layer 2 recurrence only
    layer_kernel<<<lgrid, 256, LAYER_SMEM>>>(xpA, Wh2, nullptr, nullptr, nullptr, hx, bar, 2);
    // head
    final_kernel<<<Bb, 128>>>(hx, Wf, bf, out);
}

// round 14
// speedup vs baseline: 1.0571x; 1.0571x over previous
#include <cuda_runtime.h>
#include <math.h>

#define Bb 256
#define Tt 256
#define Dd 64
#define Hh 512
#define NCT 32                     // cols per CTA tile

typedef unsigned long long ull;

// Scratch (device globals: allocation-free rule).
__device__ float g_xp[(size_t)Bb * Tt * Hh];   // xp buffer A
__device__ float g_xq[(size_t)Bb * Tt * Hh];   // xp buffer B
__device__ float g_hx[2 * Bb * Hh];            // 1MB L2-hot h exchange (double)
__device__ int   g_bar[3 * 8];                 // per (layer, group-of-32) counters

// ---------------- packed dual-fp32 helpers (sm_100+ f32x2) ----------------
__device__ __forceinline__ ull fma2(ull a, ull b, ull c) {
    ull d;
    asm("fma.rn.f32x2 %0, %1, %2, %3;" : "=l"(d) : "l"(a), "l"(b), "l"(c));
    return d;
}
__device__ __forceinline__ ull dup2(float x) {
    ull d;
    asm("mov.b64 %0, {%1, %2};" : "=l"(d) : "f"(x), "f"(x));
    return d;
}
__device__ __forceinline__ float2 unpack2(ull v) {
    float2 r;
    asm("mov.b64 {%0, %1}, %2;" : "=f"(r.x), "=f"(r.y) : "l"(v));
    return r;
}
__device__ __forceinline__ int ld_acquire(const int* p) {
    int v;
    asm volatile("ld.acquire.gpu.global.b32 %0, [%1];" : "=r"(v) : "l"(p));
    return v;
}
__device__ __forceinline__ void red_release_add(int* p, int v) {
    asm volatile("red.release.gpu.global.add.s32 [%0], %1;" :: "l"(p), "r"(v) : "memory");
}
__device__ __forceinline__ float fast_tanh(float x) {
    float ax = fabsf(x);
    float e;
    asm("ex2.approx.f32 %0, %1;" : "=f"(e) : "f"(ax * 2.885390082f));
    float t = 1.0f - __fdividef(2.0f, e + 1.0f);
    return copysignf(t, x);
}

__global__ void zero_bar_kernel() {
    if (threadIdx.x < 24) g_bar[threadIdx.x] = 0;
}

// ---------------------------------------------------------------------------
// Projection GEMM for layer 0 only: out[M,Hh] = A[M,64] @ W[64,Hh] + bias
// ---------------------------------------------------------------------------
template <int K>
__global__ __launch_bounds__(256) void proj_kernel(
    const float* __restrict__ A, const float* __restrict__ W,
    const float* __restrict__ bias, float* __restrict__ out)
{
    __shared__ float sA[16 * 132];
    __shared__ float sB[16 * 128];

    const int n0 = blockIdx.x * 128;
    const int m0 = blockIdx.y * 128;
    const int tid = threadIdx.x;
    const int tx = tid & 15;
    const int ty = tid >> 4;

    const int arow = tid >> 1;
    const int ak   = (tid & 1) * 8;
    const int bk   = tid >> 4;
    const int bc   = (tid & 15) * 8;

    ull acc[8][4];
#pragma unroll
    for (int i = 0; i < 8; i++)
#pragma unroll
        for (int j = 0; j < 4; j++) acc[i][j] = 0ull;

    float4 va0 = *(const float4*)&A[(size_t)(m0 + arow) * K + ak];
    float4 va1 = *(const float4*)&A[(size_t)(m0 + arow) * K + ak + 4];
    float4 vb0 = *(const float4*)&W[(size_t)bk * Hh + n0 + bc];
    float4 vb1 = *(const float4*)&W[(size_t)bk * Hh + n0 + bc + 4];

    const int NB = K / 16;
    for (int kb = 0; kb < NB; kb++) {
        sA[(ak + 0) * 132 + arow] = va0.x;
        sA[(ak + 1) * 132 + arow] = va0.y;
        sA[(ak + 2) * 132 + arow] = va0.z;
        sA[(ak + 3) * 132 + arow] = va0.w;
        sA[(ak + 4) * 132 + arow] = va1.x;
        sA[(ak + 5) * 132 + arow] = va1.y;
        sA[(ak + 6) * 132 + arow] = va1.z;
        sA[(ak + 7) * 132 + arow] = va1.w;
        *(float4*)&sB[bk * 128 + bc]     = vb0;
        *(float4*)&sB[bk * 128 + bc + 4] = vb1;
        __syncthreads();

        if (kb + 1 < NB) {
            int k0 = (kb + 1) * 16;
            va0 = *(const float4*)&A[(size_t)(m0 + arow) * K + k0 + ak];
            va1 = *(const float4*)&A[(size_t)(m0 + arow) * K + k0 + ak + 4];
            vb0 = *(const float4*)&W[(size_t)(k0 + bk) * Hh + n0 + bc];
            vb1 = *(const float4*)&W[(size_t)(k0 + bk) * Hh + n0 + bc + 4];
        }

#pragma unroll
        for (int kk = 0; kk < 16; kk++) {
            float4 a0 = *(const float4*)&sA[kk * 132 + ty * 8];
            float4 a1 = *(const float4*)&sA[kk * 132 + ty * 8 + 4];
            ulonglong2 b0 = *(const ulonglong2*)&sB[kk * 128 + tx * 8];
            ulonglong2 b1 = *(const ulonglong2*)&sB[kk * 128 + tx * 8 + 4];
            float ar[8] = {a0.x, a0.y, a0.z, a0.w, a1.x, a1.y, a1.z, a1.w};
#pragma unroll
            for (int r = 0; r < 8; r++) {
                ull av = dup2(ar[r]);
                acc[r][0] = fma2(av, b0.x, acc[r][0]);
                acc[r][1] = fma2(av, b0.y, acc[r][1]);
                acc[r][2] = fma2(av, b1.x, acc[r][2]);
                acc[r][3] = fma2(av, b1.y, acc[r][3]);
            }
        }
        __syncthreads();
    }

    float4 bi0 = *(const float4*)&bias[n0 + tx * 8];
    float4 bi1 = *(const float4*)&bias[n0 + tx * 8 + 4];
#pragma unroll
    for (int r = 0; r < 8; r++) {
        float2 u0 = unpack2(acc[r][0]);
        float2 u1 = unpack2(acc[r][1]);
        float2 u2 = unpack2(acc[r][2]);
        float2 u3 = unpack2(acc[r][3]);
        float4 o0, o1;
        o0.x = u0.x + bi0.x; o0.y = u0.y + bi0.y; o0.z = u1.x + bi0.z; o0.w = u1.y + bi0.w;
        o1.x = u2.x + bi1.x; o1.y = u2.y + bi1.y; o1.z = u3.x + bi1.z; o1.w = u3.y + bi1.w;
        size_t base = (size_t)(m0 + ty * 8 + r) * Hh + n0 + tx * 8;
        *(float4*)&out[base]     = o0;
        *(float4*)&out[base + 4] = o1;
    }
}

// ---------------------------------------------------------------------------
// Fused persistent layer kernel (R7 structure; one redundant barrier
// removed in the filler — sync C already orders sRed reads before the
// filler's sRed writes).  == R12, the verified best.
// Grid (16 col-tiles of 32 x 8 groups of 32 rows) = 128 CTAs, 256 threads.
// ---------------------------------------------------------------------------
#define SH_STR  514
#define RED_STR 34
#define SWH_F   (512 * NCT)             // 16384 floats
#define SH_F    (32 * SH_STR)           // 16448
#define RED_F   (4 * 32 * RED_STR)      // 4352
#define LAYER_SMEM ((2 * SWH_F + SH_F + RED_F) * 4)   // 214272 B

extern __shared__ float s_mem[];

__global__ __launch_bounds__(256, 1) void layer_kernel(
    const float* __restrict__ xp,  const float* __restrict__ Wh,
    const float* __restrict__ Wx,  const float* __restrict__ bnext,
    float* __restrict__ xpo,       float* __restrict__ hx,
    int* __restrict__ bar, int layer)
{
    float* sWh  = s_mem;                       // [512][32]
    float* sWx  = s_mem + SWH_F;               // [512][32]
    float* sH   = s_mem + 2 * SWH_F;           // [32][514]
    float* sRed = s_mem + 2 * SWH_F + SH_F;    // [4][32][34]

    const int n0 = blockIdx.x * NCT;
    const int b0 = blockIdx.y * 32;
    int* cnt = &bar[layer * 8 + blockIdx.y];

    const int tid  = threadIdx.x;
    const int w    = tid >> 5;
    const int lane = tid & 31;
    const int kc   = w >> 1;             // k-chunk 0..3 (128 k each)
    const int rh   = w & 1;              // row half (16 rows)
    const int rg   = lane >> 3;          // row group of 4 within half
    const int cg   = lane & 7;           // 8 col groups of 4
    const int kbase = kc * 128;
    const int rbase = rh * 16 + rg * 4;

    const int er = tid >> 3;             // epilogue row 0..31
    const int ec = (tid & 7) * 4;        // epilogue col group

    // ---- stage Wh (and Wx_next) column slices once ----
    for (int i = tid; i < 512 * 8; i += 256) {     // 4096 float4 slots
        int k = i >> 3, c4 = i & 7;
        float4 v = *(const float4*)&Wh[(size_t)k * Hh + n0 + c4 * 4];
        *(float4*)&sWh[k * NCT + c4 * 4] = v;
    }
    if (Wx) {
        for (int i = tid; i < 512 * 8; i += 256) {
            int k = i >> 3, c4 = i & 7;
            float4 v = *(const float4*)&Wx[(size_t)k * Hh + n0 + c4 * 4];
            *(float4*)&sWx[k * NCT + c4 * 4] = v;
        }
    }
    float4 bv = make_float4(0.f, 0.f, 0.f, 0.f);
    if (Wx) bv = *(const float4*)&bnext[n0 + ec];

    // ---- t = 0: h0 = tanh(xp0) -> hx[0] ----
    {
        size_t base = ((size_t)(b0 + er) * Tt) * Hh + n0 + ec;
        float4 xv = *(const float4*)&xp[base];
        float4 o;
        o.x = fast_tanh(xv.x); o.y = fast_tanh(xv.y);
        o.z = fast_tanh(xv.z); o.w = fast_tanh(xv.w);
        __stcg((float4*)&hx[(size_t)(b0 + er) * Hh + n0 + ec], o);
    }
    __syncthreads();                 // weights staged + h0 issued
    if (tid == 0) red_release_add(cnt, 1);

    for (int t = 1; t < Tt; t++) {
        // prefetch xp for this step (independent of the flag)
        size_t obase = (((size_t)(b0 + er) * Tt) + t) * Hh + n0 + ec;
        float4 xv = *(const float4*)&xp[obase];

        // ---- wait for all 16 producers of h_{t-1} ----
        if (tid == 0) {
            while (ld_acquire(cnt) < 16 * t) { }
        }
        __syncthreads();

        // ---- stage h_{t-1}[b0..b0+31, :] from hx ----
        {
            const float* src = hx + ((size_t)((t - 1) & 1)) * (Bb * Hh);
#pragma unroll
            for (int half = 0; half < 2; half++) {
                float4 sv[8];
#pragma unroll
                for (int j = 0; j < 8; j++) {
                    int slot = tid + (half * 8 + j) * 256;
                    int row = slot >> 7, k4 = slot & 127;
                    sv[j] = __ldcg((const float4*)&src[(size_t)(b0 + row) * Hh + k4 * 4]);
                }
#pragma unroll
                for (int j = 0; j < 8; j++) {
                    int slot = tid + (half * 8 + j) * 256;
                    int row = slot >> 7, k4 = slot & 127;
                    float* d = &sH[row * SH_STR + k4 * 4];
                    *(float2*)&d[0] = make_float2(sv[j].x, sv[j].y);
                    *(float2*)&d[2] = make_float2(sv[j].z, sv[j].w);
                }
            }
        }
        __syncthreads();

        // ---- recurrence compute: warp (kc, rh): [16 rows x 32 cols], 128 k ----
        {
            ull a00 = 0, a01 = 0, a10 = 0, a11 = 0,
                a20 = 0, a21 = 0, a30 = 0, a31 = 0;
            const float* hp = &sH[rbase * SH_STR + kbase];
            const float* wp = &sWh[kbase * NCT];
#pragma unroll 8
            for (int kk = 0; kk < 128; kk += 2) {
                float2 h0 = *(const float2*)&hp[kk];
                float2 h1 = *(const float2*)&hp[SH_STR + kk];
                float2 h2 = *(const float2*)&hp[2 * SH_STR + kk];
                float2 h3 = *(const float2*)&hp[3 * SH_STR + kk];
                ulonglong2 wa = *(const ulonglong2*)&wp[kk * NCT + cg * 4];
                ulonglong2 wb = *(const ulonglong2*)&wp[(kk + 1) * NCT + cg * 4];
                ull a;
                a = dup2(h0.x); a00 = fma2(a, wa.x, a00); a01 = fma2(a, wa.y, a01);
                a = dup2(h1.x); a10 = fma2(a, wa.x, a10); a11 = fma2(a, wa.y, a11);
                a = dup2(h2.x); a20 = fma2(a, wa.x, a20); a21 = fma2(a, wa.y, a21);
                a = dup2(h3.x); a30 = fma2(a, wa.x, a30); a31 = fma2(a, wa.y, a31);
                a = dup2(h0.y); a00 = fma2(a, wb.x, a00); a01 = fma2(a, wb.y, a01);
                a = dup2(h1.y); a10 = fma2(a, wb.x, a10); a11 = fma2(a, wb.y, a11);
                a = dup2(h2.y); a20 = fma2(a, wb.x, a20); a21 = fma2(a, wb.y, a21);
                a = dup2(h3.y); a30 = fma2(a, wb.x, a30); a31 = fma2(a, wb.y, a31);
            }
            float* d0 = &sRed[kc * (32 * RED_STR) + (rbase + 0) * RED_STR + cg * 4];
            float* d1 = &sRed[kc * (32 * RED_STR) + (rbase + 1) * RED_STR + cg * 4];
            float* d2 = &sRed[kc * (32 * RED_STR) + (rbase + 2) * RED_STR + cg * 4];
            float* d3 = &sRed[kc * (32 * RED_STR) + (rbase + 3) * RED_STR + cg * 4];
            *(ull*)&d0[0] = a00; *(ull*)&d0[2] = a01;
            *(ull*)&d1[0] = a10; *(ull*)&d1[2] = a11;
            *(ull*)&d2[0] = a20; *(ull*)&d2[2] = a21;
            *(ull*)&d3[0] = a30; *(ull*)&d3[2] = a31;
        }
        __syncthreads();

        // ---- reduce 4 partials, add xp, tanh, store h_t to hx ----
        {
            float2 s0 = make_float2(0.f, 0.f), s1 = make_float2(0.f, 0.f);
            int rb = er * RED_STR + ec;
#pragma unroll
            for (int q = 0; q < 4; q++) {
                float2 u0 = unpack2(*(const ull*)&sRed[q * (32 * RED_STR) + rb]);
                float2 u1 = unpack2(*(const ull*)&sRed[q * (32 * RED_STR) + rb + 2]);
                s0.x += u0.x; s0.y += u0.y; s1.x += u1.x; s1.y += u1.y;
            }
            float4 o;
            o.x = fast_tanh(s0.x + xv.x); o.y = fast_tanh(s0.y + xv.y);
            o.z = fast_tanh(s1.x + xv.z); o.w = fast_tanh(s1.y + xv.w);
            __stcg((float4*)&hx[((size_t)(t & 1)) * (Bb * Hh)
                                + (size_t)(b0 + er) * Hh + n0 + ec], o);
        }
        __syncthreads();                     // sync C: stores issued before release
        if (tid == 0) red_release_add(cnt, 1);

        // ---- FILLER: next layer's projection of h_{t-1} (sH still intact) ----
        if (Wx) {
            ull a00 = 0, a01 = 0, a10 = 0, a11 = 0,
                a20 = 0, a21 = 0, a30 = 0, a31 = 0;
            const float* hp = &sH[rbase * SH_STR + kbase];
            const float* wp = &sWx[kbase * NCT];
#pragma unroll 8
            for (int kk = 0; kk < 128; kk += 2) {
                float2 h0 = *(const float2*)&hp[kk];
                float2 h1 = *(const float2*)&hp[SH_STR + kk];
                float2 h2 = *(const float2*)&hp[2 * SH_STR + kk];
                float2 h3 = *(const float2*)&hp[3 * SH_STR + kk];
                ulonglong2 wa = *(const ulonglong2*)&wp[kk * NCT + cg * 4];
                ulonglong2 wb = *(const ulonglong2*)&wp[(kk + 1) * NCT + cg * 4];
                ull a;
                a = dup2(h0.x); a00 = fma2(a, wa.x, a00); a01 = fma2(a, wa.y, a01);
                a = dup2(h1.x); a10 = fma2(a, wa.x, a10); a11 = fma2(a, wa.y, a11);
                a = dup2(h2.x); a20 = fma2(a, wa.x, a20); a21 = fma2(a, wa.y, a21);
                a = dup2(h3.x); a30 = fma2(a, wa.x, a30); a31 = fma2(a, wa.y, a31);
                a = dup2(h0.y); a00 = fma2(a, wb.x, a00); a01 = fma2(a, wb.y, a01);
                a = dup2(h1.y); a10 = fma2(a, wb.x, a10); a11 = fma2(a, wb.y, a11);
                a = dup2(h2.y); a20 = fma2(a, wb.x, a20); a21 = fma2(a, wb.y, a21);
                a = dup2(h3.y); a30 = fma2(a, wb.x, a30); a31 = fma2(a, wb.y, a31);
            }
            // NOTE: no barrier here — sync C already ordered the recurrence's
            // sRed reads before these writes (provable, not a scheduling guess).
            float* d0 = &sRed[kc * (32 * RED_STR) + (rbase + 0) * RED_STR + cg * 4];
            float* d1 = &sRed[kc * (32 * RED_STR) + (rbase + 1) * RED_STR + cg * 4];
            float* d2 = &sRed[kc * (32 * RED_STR) + (rbase + 2) * RED_STR + cg * 4];
            float* d3 = &sRed[kc * (32 * RED_STR) + (rbase + 3) * RED_STR + cg * 4];
            *(ull*)&d0[0] = a00; *(ull*)&d0[2] = a01;
            *(ull*)&d1[0] = a10; *(ull*)&d1[2] = a11;
            *(ull*)&d2[0] = a20; *(ull*)&d2[2] = a21;
            *(ull*)&d3[0] = a30; *(ull*)&d3[2] = a31;
            __syncthreads();
            float2 s0 = make_float2(0.f, 0.f), s1 = make_float2(0.f, 0.f);
            int rb = er * RED_STR + ec;
#pragma unroll
            for (int q = 0; q < 4; q++) {
                float2 u0 = unpack2(*(const ull*)&sRed[q * (32 * RED_STR) + rb]);
                float2 u1 = unpack2(*(const ull*)&sRed[q * (32 * RED_STR) + rb + 2]);
                s0.x += u0.x; s0.y += u0.y; s1.x += u1.x; s1.y += u1.y;
            }
            float4 o;
            o.x = s0.x + bv.x; o.y = s0.y + bv.y;
            o.z = s1.x + bv.z; o.w = s1.y + bv.w;
            *(float4*)&xpo[(((size_t)(b0 + er) * Tt) + (t - 1)) * Hh + n0 + ec] = o;
        }
    }

    // ---- tail: projection of h_{Tt-1} ----
    if (Wx) {
        if (tid == 0) {
            while (ld_acquire(cnt) < 16 * Tt) { }
        }
        __syncthreads();
        {
            const float* src = hx + ((size_t)((Tt - 1) & 1)) * (Bb * Hh);
#pragma unroll
            for (int half = 0; half < 2; half++) {
                float4 sv[8];
#pragma unroll
                for (int j = 0; j < 8; j++) {
                    int slot = tid + (half * 8 + j) * 256;
                    int row = slot >> 7, k4 = slot & 127;
                    sv[j] = __ldcg((const float4*)&src[(size_t)(b0 + row) * Hh + k4 * 4]);
                }
#pragma unroll
                for (int j = 0; j < 8; j++) {
                    int slot = tid + (half * 8 + j) * 256;
                    int row = slot >> 7, k4 = slot & 127;
                    float* d = &sH[row * SH_STR + k4 * 4];
                    *(float2*)&d[0] = make_float2(sv[j].x, sv[j].y);
                    *(float2*)&d[2] = make_float2(sv[j].z, sv[j].w);
                }
            }
        }
        __syncthreads();
        {
            ull a00 = 0, a01 = 0, a10 = 0, a11 = 0,
                a20 = 0, a21 = 0, a30 = 0, a31 = 0;
            const float* hp = &sH[rbase * SH_STR + kbase];
            const float* wp = &sWx[kbase * NCT];
#pragma unroll 8
            for (int kk = 0; kk < 128; kk += 2) {
                float2 h0 = *(const float2*)&hp[kk];
                float2 h1 = *(const float2*)&hp[SH_STR + kk];
                float2 h2 = *(const float2*)&hp[2 * SH_STR + kk];
                float2 h3 = *(const float2*)&hp[3 * SH_STR + kk];
                ulonglong2 wa = *(const ulonglong2*)&wp[kk * NCT + cg * 4];
                ulonglong2 wb = *(const ulonglong2*)&wp[(kk + 1) * NCT + cg * 4];
                ull a;
                a = dup2(h0.x); a00 = fma2(a, wa.x, a00); a01 = fma2(a, wa.y, a01);
                a = dup2(h1.x); a10 = fma2(a, wa.x, a10); a11 = fma2(a, wa.y, a11);
                a = dup2(h2.x); a20 = fma2(a, wa.x, a20); a21 = fma2(a, wa.y, a21);
                a = dup2(h3.x); a30 = fma2(a, wa.x, a30); a31 = fma2(a, wa.y, a31);
                a = dup2(h0.y); a00 = fma2(a, wb.x, a00); a01 = fma2(a, wb.y, a01);
                a = dup2(h1.y); a10 = fma2(a, wb.x, a10); a11 = fma2(a, wb.y, a11);
                a = dup2(h2.y); a20 = fma2(a, wb.x, a20); a21 = fma2(a, wb.y, a21);
                a = dup2(h3.y); a30 = fma2(a, wb.x, a30); a31 = fma2(a, wb.y, a31);
            }
            float* d0 = &sRed[kc * (32 * RED_STR) + (rbase + 0) * RED_STR + cg * 4];
            float* d1 = &sRed[kc * (32 * RED_STR) + (rbase + 1) * RED_STR + cg * 4];
            float* d2 = &sRed[kc * (32 * RED_STR) + (rbase + 2) * RED_STR + cg * 4];
            float* d3 = &sRed[kc * (32 * RED_STR) + (rbase + 3) * RED_STR + cg * 4];
            *(ull*)&d0[0] = a00; *(ull*)&d0[2] = a01;
            *(ull*)&d1[0] = a10; *(ull*)&d1[2] = a11;
            *(ull*)&d2[0] = a20; *(ull*)&d2[2] = a21;
            *(ull*)&d3[0] = a30; *(ull*)&d3[2] = a31;
            __syncthreads();
            float2 s0 = make_float2(0.f, 0.f), s1 = make_float2(0.f, 0.f);
            int rb = er * RED_STR + ec;
#pragma unroll
            for (int q = 0; q < 4; q++) {
                float2 u0 = unpack2(*(const ull*)&sRed[q * (32 * RED_STR) + rb]);
                float2 u1 = unpack2(*(const ull*)&sRed[q * (32 * RED_STR) + rb + 2]);
                s0.x += u0.x; s0.y += u0.y; s1.x += u1.x; s1.y += u1.y;
            }
            float4 o;
            o.x = s0.x + bv.x; o.y = s0.y + bv.y;
            o.z = s1.x + bv.z; o.w = s1.y + bv.w;
            *(float4*)&xpo[(((size_t)(b0 + er) * Tt) + (Tt - 1)) * Hh + n0 + ec] = o;
        }
    }
}

// ---------------------------------------------------------------------------
// Final: out[b] = hx[1][b,:] @ Wf + bf   (h at t=255, parity 1)
// ---------------------------------------------------------------------------
__global__ void final_kernel(const float* __restrict__ hx, const float* __restrict__ Wf,
                             const float* __restrict__ bf, float* __restrict__ out)
{
    int b = blockIdx.x;
    const float* row = hx + (size_t)(Bb * Hh) + (size_t)b * Hh;
    float s = 0.f;
    for (int j = threadIdx.x; j < Hh; j += 128) s += row[j] * Wf[j];
#pragma unroll
    for (int o = 16; o > 0; o >>= 1) s += __shfl_down_sync(0xffffffffu, s, o);
    __shared__ float ws[4];
    if ((threadIdx.x & 31) == 0) ws[threadIdx.x >> 5] = s;
    __syncthreads();
    if (threadIdx.x == 0) out[b] = ws[0] + ws[1] + ws[2] + ws[3] + bf[0];
}

// ---------------------------------------------------------------------------
extern "C" void kernel_launch(void* const* d_in, const int* in_sizes, int n_in,
                              void* d_out, int out_size)
{
    const float* x    = (const float*)d_in[0];
    const float* Wx0  = (const float*)d_in[1];
    const float* Wh0  = (const float*)d_in[2];
    const float* bi0  = (const float*)d_in[3];
    const float* Wx1  = (const float*)d_in[4];
    const float* Wh1  = (const float*)d_in[5];
    const float* bi1  = (const float*)d_in[6];
    const float* Wx2  = (const float*)d_in[7];
    const float* Wh2  = (const float*)d_in[8];
    const float* bi2  = (const float*)d_in[9];
    const float* Wf   = (const float*)d_in[10];
    const float* bf   = (const float*)d_in[11];
    float* out = (float*)d_out;

    void* p;
    cudaGetSymbolAddress(&p, g_xp);
    float* xpA = (float*)p;
    cudaGetSymbolAddress(&p, g_xq);
    float* xpB = (float*)p;
    cudaGetSymbolAddress(&p, g_hx);
    float* hx = (float*)p;
    cudaGetSymbolAddress(&p, g_bar);
    int* bar = (int*)p;

    cudaFuncSetAttribute(layer_kernel, cudaFuncAttributeMaxDynamicSharedMemorySize, LAYER_SMEM);

    dim3 pgrid(Hh / 128, (Bb * Tt) / 128);   // (4, 512)
    dim3 lgrid(Hh / NCT, Bb / 32);           // (16, 8) = 128 CTAs

    zero_bar_kernel<<<1, 32>>>();

    // layer 0 input projection (K=64)
    proj_kernel<Dd><<<pgrid, 256>>>(x, Wx0, bi0, xpA);
    // layer 0 recurrence + fused projection for layer 1
    layer_kernel<<<lgrid, 256, LAYER_SMEM>>>(xpA, Wh0, Wx1, bi1, xpB, hx, bar, 0);
    // layer 1 recurrence + fused projection for layer 2
    layer_kernel<<<lgrid, 256, LAYER_SMEM>>>(xpB, Wh1, Wx2, bi2, xpA, hx, bar, 1);
    // layer 2 recurrence only
    layer_kernel<<<lgrid, 256, LAYER_SMEM>>>(xpA, Wh2, nullptr, nullptr, nullptr, hx, bar, 2);
    // head
    final_kernel<<<Bb, 128>>>(hx, Wf, bf, out);
}

// round 15
// speedup vs baseline: 1.0574x; 1.0003x over previous
#include <cuda_runtime.h>
#include <math.h>

#define Bb 256
#define Tt 256
#define Dd 64
#define Hh 512
#define NCT 32                     // cols per CTA tile

typedef unsigned long long ull;

// Scratch (device globals: allocation-free rule).
__device__ float g_xp[(size_t)Bb * Tt * Hh];   // xp buffer A
__device__ float g_xq[(size_t)Bb * Tt * Hh];   // xp buffer B
__device__ float g_hx[2 * Bb * Hh];            // 1MB L2-hot h exchange (double)
__device__ int   g_bar[3 * 8];                 // per (layer, group-of-32) counters

// ---------------- packed dual-fp32 helpers (sm_100+ f32x2) ----------------
__device__ __forceinline__ ull fma2(ull a, ull b, ull c) {
    ull d;
    asm("fma.rn.f32x2 %0, %1, %2, %3;" : "=l"(d) : "l"(a), "l"(b), "l"(c));
    return d;
}
__device__ __forceinline__ ull dup2(float x) {
    ull d;
    asm("mov.b64 %0, {%1, %2};" : "=l"(d) : "f"(x), "f"(x));
    return d;
}
__device__ __forceinline__ float2 unpack2(ull v) {
    float2 r;
    asm("mov.b64 {%0, %1}, %2;" : "=f"(r.x), "=f"(r.y) : "l"(v));
    return r;
}
__device__ __forceinline__ int ld_acquire(const int* p) {
    int v;
    asm volatile("ld.acquire.gpu.global.b32 %0, [%1];" : "=r"(v) : "l"(p));
    return v;
}
__device__ __forceinline__ void red_release_add(int* p, int v) {
    asm volatile("red.release.gpu.global.add.s32 [%0], %1;" :: "l"(p), "r"(v) : "memory");
}
__device__ __forceinline__ float fast_tanh(float x) {
    float ax = fabsf(x);
    float e;
    asm("ex2.approx.f32 %0, %1;" : "=f"(e) : "f"(ax * 2.885390082f));
    float t = 1.0f - __fdividef(2.0f, e + 1.0f);
    return copysignf(t, x);
}

__global__ void zero_bar_kernel() {
    if (threadIdx.x < 24) g_bar[threadIdx.x] = 0;
}

// ---------------------------------------------------------------------------
// Projection GEMM for layer 0 only: out[M,Hh] = A[M,64] @ W[64,Hh] + bias
// ---------------------------------------------------------------------------
template <int K>
__global__ __launch_bounds__(256) void proj_kernel(
    const float* __restrict__ A, const float* __restrict__ W,
    const float* __restrict__ bias, float* __restrict__ out)
{
    __shared__ float sA[16 * 132];
    __shared__ float sB[16 * 128];

    const int n0 = blockIdx.x * 128;
    const int m0 = blockIdx.y * 128;
    const int tid = threadIdx.x;
    const int tx = tid & 15;
    const int ty = tid >> 4;

    const int arow = tid >> 1;
    const int ak   = (tid & 1) * 8;
    const int bk   = tid >> 4;
    const int bc   = (tid & 15) * 8;

    ull acc[8][4];
#pragma unroll
    for (int i = 0; i < 8; i++)
#pragma unroll
        for (int j = 0; j < 4; j++) acc[i][j] = 0ull;

    float4 va0 = *(const float4*)&A[(size_t)(m0 + arow) * K + ak];
    float4 va1 = *(const float4*)&A[(size_t)(m0 + arow) * K + ak + 4];
    float4 vb0 = *(const float4*)&W[(size_t)bk * Hh + n0 + bc];
    float4 vb1 = *(const float4*)&W[(size_t)bk * Hh + n0 + bc + 4];

    const int NB = K / 16;
    for (int kb = 0; kb < NB; kb++) {
        sA[(ak + 0) * 132 + arow] = va0.x;
        sA[(ak + 1) * 132 + arow] = va0.y;
        sA[(ak + 2) * 132 + arow] = va0.z;
        sA[(ak + 3) * 132 + arow] = va0.w;
        sA[(ak + 4) * 132 + arow] = va1.x;
        sA[(ak + 5) * 132 + arow] = va1.y;
        sA[(ak + 6) * 132 + arow] = va1.z;
        sA[(ak + 7) * 132 + arow] = va1.w;
        *(float4*)&sB[bk * 128 + bc]     = vb0;
        *(float4*)&sB[bk * 128 + bc + 4] = vb1;
        __syncthreads();

        if (kb + 1 < NB) {
            int k0 = (kb + 1) * 16;
            va0 = *(const float4*)&A[(size_t)(m0 + arow) * K + k0 + ak];
            va1 = *(const float4*)&A[(size_t)(m0 + arow) * K + k0 + ak + 4];
            vb0 = *(const float4*)&W[(size_t)(k0 + bk) * Hh + n0 + bc];
            vb1 = *(const float4*)&W[(size_t)(k0 + bk) * Hh + n0 + bc + 4];
        }

#pragma unroll
        for (int kk = 0; kk < 16; kk++) {
            float4 a0 = *(const float4*)&sA[kk * 132 + ty * 8];
            float4 a1 = *(const float4*)&sA[kk * 132 + ty * 8 + 4];
            ulonglong2 b0 = *(const ulonglong2*)&sB[kk * 128 + tx * 8];
            ulonglong2 b1 = *(const ulonglong2*)&sB[kk * 128 + tx * 8 + 4];
            float ar[8] = {a0.x, a0.y, a0.z, a0.w, a1.x, a1.y, a1.z, a1.w};
#pragma unroll
            for (int r = 0; r < 8; r++) {
                ull av = dup2(ar[r]);
                acc[r][0] = fma2(av, b0.x, acc[r][0]);
                acc[r][1] = fma2(av, b0.y, acc[r][1]);
                acc[r][2] = fma2(av, b1.x, acc[r][2]);
                acc[r][3] = fma2(av, b1.y, acc[r][3]);
            }
        }
        __syncthreads();
    }

    float4 bi0 = *(const float4*)&bias[n0 + tx * 8];
    float4 bi1 = *(const float4*)&bias[n0 + tx * 8 + 4];
#pragma unroll
    for (int r = 0; r < 8; r++) {
        float2 u0 = unpack2(acc[r][0]);
        float2 u1 = unpack2(acc[r][1]);
        float2 u2 = unpack2(acc[r][2]);
        float2 u3 = unpack2(acc[r][3]);
        float4 o0, o1;
        o0.x = u0.x + bi0.x; o0.y = u0.y + bi0.y; o0.z = u1.x + bi0.z; o0.w = u1.y + bi0.w;
        o1.x = u2.x + bi1.x; o1.y = u2.y + bi1.y; o1.z = u3.x + bi1.z; o1.w = u3.y + bi1.w;
        size_t base = (size_t)(m0 + ty * 8 + r) * Hh + n0 + tx * 8;
        *(float4*)&out[base]     = o0;
        *(float4*)&out[base + 4] = o1;
    }
}

// ---------------------------------------------------------------------------
// Fused persistent layer kernel (R12 structure; SH_STR 514->516 so h staging
// uses single float4 STS — mm reads of sH are lane-invariant broadcasts, so
// the stride change provably cannot affect the compute loops).
// Grid (16 col-tiles of 32 x 8 groups of 32 rows) = 128 CTAs, 256 threads.
// ---------------------------------------------------------------------------
#define SH_STR  516
#define RED_STR 34
#define SWH_F   (512 * NCT)             // 16384 floats
#define SH_F    (32 * SH_STR)           // 16512
#define RED_F   (4 * 32 * RED_STR)      // 4352
#define LAYER_SMEM ((2 * SWH_F + SH_F + RED_F) * 4)   // 214528 B

extern __shared__ float s_mem[];

__global__ __launch_bounds__(256, 1) void layer_kernel(
    const float* __restrict__ xp,  const float* __restrict__ Wh,
    const float* __restrict__ Wx,  const float* __restrict__ bnext,
    float* __restrict__ xpo,       float* __restrict__ hx,
    int* __restrict__ bar, int layer)
{
    float* sWh  = s_mem;                       // [512][32]
    float* sWx  = s_mem + SWH_F;               // [512][32]
    float* sH   = s_mem + 2 * SWH_F;           // [32][516]
    float* sRed = s_mem + 2 * SWH_F + SH_F;    // [4][32][34]

    const int n0 = blockIdx.x * NCT;
    const int b0 = blockIdx.y * 32;
    int* cnt = &bar[layer * 8 + blockIdx.y];

    const int tid  = threadIdx.x;
    const int w    = tid >> 5;
    const int lane = tid & 31;
    const int kc   = w >> 1;             // k-chunk 0..3 (128 k each)
    const int rh   = w & 1;              // row half (16 rows)
    const int rg   = lane >> 3;          // row group of 4 within half
    const int cg   = lane & 7;           // 8 col groups of 4
    const int kbase = kc * 128;
    const int rbase = rh * 16 + rg * 4;

    const int er = tid >> 3;             // epilogue row 0..31
    const int ec = (tid & 7) * 4;        // epilogue col group

    // ---- stage Wh (and Wx_next) column slices once ----
    for (int i = tid; i < 512 * 8; i += 256) {     // 4096 float4 slots
        int k = i >> 3, c4 = i & 7;
        float4 v = *(const float4*)&Wh[(size_t)k * Hh + n0 + c4 * 4];
        *(float4*)&sWh[k * NCT + c4 * 4] = v;
    }
    if (Wx) {
        for (int i = tid; i < 512 * 8; i += 256) {
            int k = i >> 3, c4 = i & 7;
            float4 v = *(const float4*)&Wx[(size_t)k * Hh + n0 + c4 * 4];
            *(float4*)&sWx[k * NCT + c4 * 4] = v;
        }
    }
    float4 bv = make_float4(0.f, 0.f, 0.f, 0.f);
    if (Wx) bv = *(const float4*)&bnext[n0 + ec];

    // ---- t = 0: h0 = tanh(xp0) -> hx[0] ----
    {
        size_t base = ((size_t)(b0 + er) * Tt) * Hh + n0 + ec;
        float4 xv = *(const float4*)&xp[base];
        float4 o;
        o.x = fast_tanh(xv.x); o.y = fast_tanh(xv.y);
        o.z = fast_tanh(xv.z); o.w = fast_tanh(xv.w);
        __stcg((float4*)&hx[(size_t)(b0 + er) * Hh + n0 + ec], o);
    }
    __syncthreads();                 // weights staged + h0 issued
    if (tid == 0) red_release_add(cnt, 1);

    for (int t = 1; t < Tt; t++) {
        // prefetch xp for this step (independent of the flag)
        size_t obase = (((size_t)(b0 + er) * Tt) + t) * Hh + n0 + ec;
        float4 xv = *(const float4*)&xp[obase];

        // ---- wait for all 16 producers of h_{t-1} ----
        if (tid == 0) {
            while (ld_acquire(cnt) < 16 * t) { }
        }
        __syncthreads();

        // ---- stage h_{t-1}[b0..b0+31, :] from hx (float4 STS, SH_STR%4==0) ----
        {
            const float* src = hx + ((size_t)((t - 1) & 1)) * (Bb * Hh);
#pragma unroll
            for (int half = 0; half < 2; half++) {
                float4 sv[8];
#pragma unroll
                for (int j = 0; j < 8; j++) {
                    int slot = tid + (half * 8 + j) * 256;
                    int row = slot >> 7, k4 = slot & 127;
                    sv[j] = __ldcg((const float4*)&src[(size_t)(b0 + row) * Hh + k4 * 4]);
                }
#pragma unroll
                for (int j = 0; j < 8; j++) {
                    int slot = tid + (half * 8 + j) * 256;
                    int row = slot >> 7, k4 = slot & 127;
                    *(float4*)&sH[row * SH_STR + k4 * 4] = sv[j];
                }
            }
        }
        __syncthreads();

        // ---- recurrence compute: warp (kc, rh): [16 rows x 32 cols], 128 k ----
        {
            ull a00 = 0, a01 = 0, a10 = 0, a11 = 0,
                a20 = 0, a21 = 0, a30 = 0, a31 = 0;
            const float* hp = &sH[rbase * SH_STR + kbase];
            const float* wp = &sWh[kbase * NCT];
#pragma unroll 8
            for (int kk = 0; kk < 128; kk += 2) {
                float2 h0 = *(const float2*)&hp[kk];
                float2 h1 = *(const float2*)&hp[SH_STR + kk];
                float2 h2 = *(const float2*)&hp[2 * SH_STR + kk];
                float2 h3 = *(const float2*)&hp[3 * SH_STR + kk];
                ulonglong2 wa = *(const ulonglong2*)&wp[kk * NCT + cg * 4];
                ulonglong2 wb = *(const ulonglong2*)&wp[(kk + 1) * NCT + cg * 4];
                ull a;
                a = dup2(h0.x); a00 = fma2(a, wa.x, a00); a01 = fma2(a, wa.y, a01);
                a = dup2(h1.x); a10 = fma2(a, wa.x, a10); a11 = fma2(a, wa.y, a11);
                a = dup2(h2.x); a20 = fma2(a, wa.x, a20); a21 = fma2(a, wa.y, a21);
                a = dup2(h3.x); a30 = fma2(a, wa.x, a30); a31 = fma2(a, wa.y, a31);
                a = dup2(h0.y); a00 = fma2(a, wb.x, a00); a01 = fma2(a, wb.y, a01);
                a = dup2(h1.y); a10 = fma2(a, wb.x, a10); a11 = fma2(a, wb.y, a11);
                a = dup2(h2.y); a20 = fma2(a, wb.x, a20); a21 = fma2(a, wb.y, a21);
                a = dup2(h3.y); a30 = fma2(a, wb.x, a30); a31 = fma2(a, wb.y, a31);
            }
            float* d0 = &sRed[kc * (32 * RED_STR) + (rbase + 0) * RED_STR + cg * 4];
            float* d1 = &sRed[kc * (32 * RED_STR) + (rbase + 1) * RED_STR + cg * 4];
            float* d2 = &sRed[kc * (32 * RED_STR) + (rbase + 2) * RED_STR + cg * 4];
            float* d3 = &sRed[kc * (32 * RED_STR) + (rbase + 3) * RED_STR + cg * 4];
            *(ull*)&d0[0] = a00; *(ull*)&d0[2] = a01;
            *(ull*)&d1[0] = a10; *(ull*)&d1[2] = a11;
            *(ull*)&d2[0] = a20; *(ull*)&d2[2] = a21;
            *(ull*)&d3[0] = a30; *(ull*)&d3[2] = a31;
        }
        __syncthreads();

        // ---- reduce 4 partials, add xp, tanh, store h_t to hx ----
        {
            float2 s0 = make_float2(0.f, 0.f), s1 = make_float2(0.f, 0.f);
            int rb = er * RED_STR + ec;
#pragma unroll
            for (int q = 0; q < 4; q++) {
                float2 u0 = unpack2(*(const ull*)&sRed[q * (32 * RED_STR) + rb]);
                float2 u1 = unpack2(*(const ull*)&sRed[q * (32 * RED_STR) + rb + 2]);
                s0.x += u0.x; s0.y += u0.y; s1.x += u1.x; s1.y += u1.y;
            }
            float4 o;
            o.x = fast_tanh(s0.x + xv.x); o.y = fast_tanh(s0.y + xv.y);
            o.z = fast_tanh(s1.x + xv.z); o.w = fast_tanh(s1.y + xv.w);
            __stcg((float4*)&hx[((size_t)(t & 1)) * (Bb * Hh)
                                + (size_t)(b0 + er) * Hh + n0 + ec], o);
        }
        __syncthreads();                     // sync C: stores issued before release
        if (tid == 0) red_release_add(cnt, 1);

        // ---- FILLER: next layer's projection of h_{t-1} (sH still intact) ----
        if (Wx) {
            ull a00 = 0, a01 = 0, a10 = 0, a11 = 0,
                a20 = 0, a21 = 0, a30 = 0, a31 = 0;
            const float* hp = &sH[rbase * SH_STR + kbase];
            const float* wp = &sWx[kbase * NCT];
#pragma unroll 8
            for (int kk = 0; kk < 128; kk += 2) {
                float2 h0 = *(const float2*)&hp[kk];
                float2 h1 = *(const float2*)&hp[SH_STR + kk];
                float2 h2 = *(const float2*)&hp[2 * SH_STR + kk];
                float2 h3 = *(const float2*)&hp[3 * SH_STR + kk];
                ulonglong2 wa = *(const ulonglong2*)&wp[kk * NCT + cg * 4];
                ulonglong2 wb = *(const ulonglong2*)&wp[(kk + 1) * NCT + cg * 4];
                ull a;
                a = dup2(h0.x); a00 = fma2(a, wa.x, a00); a01 = fma2(a, wa.y, a01);
                a = dup2(h1.x); a10 = fma2(a, wa.x, a10); a11 = fma2(a, wa.y, a11);
                a = dup2(h2.x); a20 = fma2(a, wa.x, a20); a21 = fma2(a, wa.y, a21);
                a = dup2(h3.x); a30 = fma2(a, wa.x, a30); a31 = fma2(a, wa.y, a31);
                a = dup2(h0.y); a00 = fma2(a, wb.x, a00); a01 = fma2(a, wb.y, a01);
                a = dup2(h1.y); a10 = fma2(a, wb.x, a10); a11 = fma2(a, wb.y, a11);
                a = dup2(h2.y); a20 = fma2(a, wb.x, a20); a21 = fma2(a, wb.y, a21);
                a = dup2(h3.y); a30 = fma2(a, wb.x, a30); a31 = fma2(a, wb.y, a31);
            }
            // NOTE: no barrier here — sync C already ordered the recurrence's
            // sRed reads before these writes (provable, not a scheduling guess).
            float* d0 = &sRed[kc * (32 * RED_STR) + (rbase + 0) * RED_STR + cg * 4];
            float* d1 = &sRed[kc * (32 * RED_STR) + (rbase + 1) * RED_STR + cg * 4];
            float* d2 = &sRed[kc * (32 * RED_STR) + (rbase + 2) * RED_STR + cg * 4];
            float* d3 = &sRed[kc * (32 * RED_STR) + (rbase + 3) * RED_STR + cg * 4];
            *(ull*)&d0[0] = a00; *(ull*)&d0[2] = a01;
            *(ull*)&d1[0] = a10; *(ull*)&d1[2] = a11;
            *(ull*)&d2[0] = a20; *(ull*)&d2[2] = a21;
            *(ull*)&d3[0] = a30; *(ull*)&d3[2] = a31;
            __syncthreads();
            float2 s0 = make_float2(0.f, 0.f), s1 = make_float2(0.f, 0.f);
            int rb = er * RED_STR + ec;
#pragma unroll
            for (int q = 0; q < 4; q++) {
                float2 u0 = unpack2(*(const ull*)&sRed[q * (32 * RED_STR) + rb]);
                float2 u1 = unpack2(*(const ull*)&sRed[q * (32 * RED_STR) + rb + 2]);
                s0.x += u0.x; s0.y += u0.y; s1.x += u1.x; s1.y += u1.y;
            }
            float4 o;
            o.x = s0.x + bv.x; o.y = s0.y + bv.y;
            o.z = s1.x + bv.z; o.w = s1.y + bv.w;
            *(float4*)&xpo[(((size_t)(b0 + er) * Tt) + (t - 1)) * Hh + n0 + ec] = o;
        }
    }

    // ---- tail: projection of h_{Tt-1} ----
    if (Wx) {
        if (tid == 0) {
            while (ld_acquire(cnt) < 16 * Tt) { }
        }
        __syncthreads();
        {
            const float* src = hx + ((size_t)((Tt - 1) & 1)) * (Bb * Hh);
#pragma unroll
            for (int half = 0; half < 2; half++) {
                float4 sv[8];
#pragma unroll
                for (int j = 0; j < 8; j++) {
                    int slot = tid + (half * 8 + j) * 256;
                    int row = slot >> 7, k4 = slot & 127;
                    sv[j] = __ldcg((const float4*)&src[(size_t)(b0 + row) * Hh + k4 * 4]);
                }
#pragma unroll
                for (int j = 0; j < 8; j++) {
                    int slot = tid + (half * 8 + j) * 256;
                    int row = slot >> 7, k4 = slot & 127;
                    *(float4*)&sH[row * SH_STR + k4 * 4] = sv[j];
                }
            }
        }
        __syncthreads();
        {
            ull a00 = 0, a01 = 0, a10 = 0, a11 = 0,
                a20 = 0, a21 = 0, a30 = 0, a31 = 0;
            const float* hp = &sH[rbase * SH_STR + kbase];
            const float* wp = &sWx[kbase * NCT];
#pragma unroll 8
            for (int kk = 0; kk < 128; kk += 2) {
                float2 h0 = *(const float2*)&hp[kk];
                float2 h1 = *(const float2*)&hp[SH_STR + kk];
                float2 h2 = *(const float2*)&hp[2 * SH_STR + kk];
                float2 h3 = *(const float2*)&hp[3 * SH_STR + kk];
                ulonglong2 wa = *(const ulonglong2*)&wp[kk * NCT + cg * 4];
                ulonglong2 wb = *(const ulonglong2*)&wp[(kk + 1) * NCT + cg * 4];
                ull a;
                a = dup2(h0.x); a00 = fma2(a, wa.x, a00); a01 = fma2(a, wa.y, a01);
                a = dup2(h1.x); a10 = fma2(a, wa.x, a10); a11 = fma2(a, wa.y, a11);
                a = dup2(h2.x); a20 = fma2(a, wa.x, a20); a21 = fma2(a, wa.y, a21);
                a = dup2(h3.x); a30 = fma2(a, wa.x, a30); a31 = fma2(a, wa.y, a31);
                a = dup2(h0.y); a00 = fma2(a, wb.x, a00); a01 = fma2(a, wb.y, a01);
                a = dup2(h1.y); a10 = fma2(a, wb.x, a10); a11 = fma2(a, wb.y, a11);
                a = dup2(h2.y); a20 = fma2(a, wb.x, a20); a21 = fma2(a, wb.y, a21);
                a = dup2(h3.y); a30 = fma2(a, wb.x, a30); a31 = fma2(a, wb.y, a31);
            }
            float* d0 = &sRed[kc * (32 * RED_STR) + (rbase + 0) * RED_STR + cg * 4];
            float* d1 = &sRed[kc * (32 * RED_STR) + (rbase + 1) * RED_STR + cg * 4];
            float* d2 = &sRed[kc * (32 * RED_STR) + (rbase + 2) * RED_STR + cg * 4];
            float* d3 = &sRed[kc * (32 * RED_STR) + (rbase + 3) * RED_STR + cg * 4];
            *(ull*)&d0[0] = a00; *(ull*)&d0[2] = a01;
            *(ull*)&d1[0] = a10; *(ull*)&d1[2] = a11;
            *(ull*)&d2[0] = a20; *(ull*)&d2[2] = a21;
            *(ull*)&d3[0] = a30; *(ull*)&d3[2] = a31;
            __syncthreads();
            float2 s0 = make_float2(0.f, 0.f), s1 = make_float2(0.f, 0.f);
            int rb = er * RED_STR + ec;
#pragma unroll
            for (int q = 0; q < 4; q++) {
                float2 u0 = unpack2(*(const ull*)&sRed[q * (32 * RED_STR) + rb]);
                float2 u1 = unpack2(*(const ull*)&sRed[q * (32 * RED_STR) + rb + 2]);
                s0.x += u0.x; s0.y += u0.y; s1.x += u1.x; s1.y += u1.y;
            }
            float4 o;
            o.x = s0.x + bv.x; o.y = s0.y + bv.y;
            o.z = s1.x + bv.z; o.w = s1.y + bv.w;
            *(float4*)&xpo[(((size_t)(b0 + er) * Tt) + (Tt - 1)) * Hh + n0 + ec] = o;
        }
    }
}

// ---------------------------------------------------------------------------
// Final: out[b] = hx[1][b,:] @ Wf + bf   (h at t=255, parity 1)
// ---------------------------------------------------------------------------
__global__ void final_kernel(const float* __restrict__ hx, const float* __restrict__ Wf,
                             const float* __restrict__ bf, float* __restrict__ out)
{
    int b = blockIdx.x;
    const float* row = hx + (size_t)(Bb * Hh) + (size_t)b * Hh;
    float s = 0.f;
    for (int j = threadIdx.x; j < Hh; j += 128) s += row[j] * Wf[j];
#pragma unroll
    for (int o = 16; o > 0; o >>= 1) s += __shfl_down_sync(0xffffffffu, s, o);
    __shared__ float ws[4];
    if ((threadIdx.x & 31) == 0) ws[threadIdx.x >> 5] = s;
    __syncthreads();
    if (threadIdx.x == 0) out[b] = ws[0] + ws[1] + ws[2] + ws[3] + bf[0];
}

// ---------------------------------------------------------------------------
extern "C" void kernel_launch(void* const* d_in, const int* in_sizes, int n_in,
                              void* d_out, int out_size)
{
    const float* x    = (const float*)d_in[0];
    const float* Wx0  = (const float*)d_in[1];
    const float* Wh0  = (const float*)d_in[2];
    const float* bi0  = (const float*)d_in[3];
    const float* Wx1  = (const float*)d_in[4];
    const float* Wh1  = (const float*)d_in[5];
    const float* bi1  = (const float*)d_in[6];
    const float* Wx2  = (const float*)d_in[7];
    const float* Wh2  = (const float*)d_in[8];
    const float* bi2  = (const float*)d_in[9];
    const float* Wf   = (const float*)d_in[10];
    const float* bf   = (const float*)d_in[11];
    float* out = (float*)d_out;

    void* p;
    cudaGetSymbolAddress(&p, g_xp);
    float* xpA = (float*)p;
    cudaGetSymbolAddress(&p, g_xq);
    float* xpB = (float*)p;
    cudaGetSymbolAddress(&p, g_hx);
    float* hx = (float*)p;
    cudaGetSymbolAddress(&p, g_bar);
    int* bar = (int*)p;

    cudaFuncSetAttribute(layer_kernel, cudaFuncAttributeMaxDynamicSharedMemorySize, LAYER_SMEM);

    dim3 pgrid(Hh / 128, (Bb * Tt) / 128);   // (4, 512)
    dim3 lgrid(Hh / NCT, Bb / 32);           // (16, 8) = 128 CTAs

    zero_bar_kernel<<<1, 32>>>();

    // layer 0 input projection (K=64)
    proj_kernel<Dd><<<pgrid, 256>>>(x, Wx0, bi0, xpA);
    // layer 0 recurrence + fused projection for layer 1
    layer_kernel<<<lgrid, 256, LAYER_SMEM>>>(xpA, Wh0, Wx1, bi1, xpB, hx, bar, 0);
    // layer 1 recurrence + fused projection for layer 2
    layer_kernel<<<lgrid, 256, LAYER_SMEM>>>(xpB, Wh1, Wx2, bi2, xpA, hx, bar, 1);
    // layer 2 recurrence only
    layer_kernel<<<lgrid, 256, LAYER_SMEM>>>(xpA, Wh2, nullptr, nullptr, nullptr, hx, bar, 2);
    // head
    final_kernel<<<Bb, 128>>>(hx, Wf, bf, out);
}

// round 16
// speedup vs baseline: 1.0591x; 1.0016x over previous
#include <cuda_runtime.h>
#include <math.h>

#define Bb 256
#define Tt 256
#define Dd 64
#define Hh 512
#define NCT 32                     // cols per CTA tile

typedef unsigned long long ull;

// Scratch (device globals: allocation-free rule).
__device__ float g_xp[(size_t)Bb * Tt * Hh];   // xp buffer A
__device__ float g_xq[(size_t)Bb * Tt * Hh];   // xp buffer B
__device__ float g_hx[2 * Bb * Hh];            // 1MB L2-hot h exchange (double)
__device__ int   g_bar[3 * 8];                 // per (layer, group-of-32) counters

// ---------------- packed dual-fp32 helpers (sm_100+ f32x2) ----------------
__device__ __forceinline__ ull fma2(ull a, ull b, ull c) {
    ull d;
    asm("fma.rn.f32x2 %0, %1, %2, %3;" : "=l"(d) : "l"(a), "l"(b), "l"(c));
    return d;
}
__device__ __forceinline__ ull dup2(float x) {
    ull d;
    asm("mov.b64 %0, {%1, %2};" : "=l"(d) : "f"(x), "f"(x));
    return d;
}
__device__ __forceinline__ float2 unpack2(ull v) {
    float2 r;
    asm("mov.b64 {%0, %1}, %2;" : "=f"(r.x), "=f"(r.y) : "l"(v));
    return r;
}
__device__ __forceinline__ int ld_acquire(const int* p) {
    int v;
    asm volatile("ld.acquire.gpu.global.b32 %0, [%1];" : "=r"(v) : "l"(p));
    return v;
}
__device__ __forceinline__ void red_release_add(int* p, int v) {
    asm volatile("red.release.gpu.global.add.s32 [%0], %1;" :: "l"(p), "r"(v) : "memory");
}
__device__ __forceinline__ float fast_tanh(float x) {
    float ax = fabsf(x);
    float e;
    asm("ex2.approx.f32 %0, %1;" : "=f"(e) : "f"(ax * 2.885390082f));
    float t = 1.0f - __fdividef(2.0f, e + 1.0f);
    return copysignf(t, x);
}

// ---------------------------------------------------------------------------
// Projection GEMM for layer 0 only: out[M,Hh] = A[M,64] @ W[64,Hh] + bias
// Block (0,0) also zeroes the inter-CTA counters (proj0 strictly precedes
// every layer_kernel in stream order, so visibility is guaranteed).
// ---------------------------------------------------------------------------
template <int K>
__global__ __launch_bounds__(256) void proj_kernel(
    const float* __restrict__ A, const float* __restrict__ W,
    const float* __restrict__ bias, float* __restrict__ out)
{
    __shared__ float sA[16 * 132];
    __shared__ float sB[16 * 128];

    const int n0 = blockIdx.x * 128;
    const int m0 = blockIdx.y * 128;
    const int tid = threadIdx.x;
    const int tx = tid & 15;
    const int ty = tid >> 4;

    if (blockIdx.x == 0 && blockIdx.y == 0 && tid < 24) g_bar[tid] = 0;

    const int arow = tid >> 1;
    const int ak   = (tid & 1) * 8;
    const int bk   = tid >> 4;
    const int bc   = (tid & 15) * 8;

    ull acc[8][4];
#pragma unroll
    for (int i = 0; i < 8; i++)
#pragma unroll
        for (int j = 0; j < 4; j++) acc[i][j] = 0ull;

    float4 va0 = *(const float4*)&A[(size_t)(m0 + arow) * K + ak];
    float4 va1 = *(const float4*)&A[(size_t)(m0 + arow) * K + ak + 4];
    float4 vb0 = *(const float4*)&W[(size_t)bk * Hh + n0 + bc];
    float4 vb1 = *(const float4*)&W[(size_t)bk * Hh + n0 + bc + 4];

    const int NB = K / 16;
    for (int kb = 0; kb < NB; kb++) {
        sA[(ak + 0) * 132 + arow] = va0.x;
        sA[(ak + 1) * 132 + arow] = va0.y;
        sA[(ak + 2) * 132 + arow] = va0.z;
        sA[(ak + 3) * 132 + arow] = va0.w;
        sA[(ak + 4) * 132 + arow] = va1.x;
        sA[(ak + 5) * 132 + arow] = va1.y;
        sA[(ak + 6) * 132 + arow] = va1.z;
        sA[(ak + 7) * 132 + arow] = va1.w;
        *(float4*)&sB[bk * 128 + bc]     = vb0;
        *(float4*)&sB[bk * 128 + bc + 4] = vb1;
        __syncthreads();

        if (kb + 1 < NB) {
            int k0 = (kb + 1) * 16;
            va0 = *(const float4*)&A[(size_t)(m0 + arow) * K + k0 + ak];
            va1 = *(const float4*)&A[(size_t)(m0 + arow) * K + k0 + ak + 4];
            vb0 = *(const float4*)&W[(size_t)(k0 + bk) * Hh + n0 + bc];
            vb1 = *(const float4*)&W[(size_t)(k0 + bk) * Hh + n0 + bc + 4];
        }

#pragma unroll
        for (int kk = 0; kk < 16; kk++) {
            float4 a0 = *(const float4*)&sA[kk * 132 + ty * 8];
            float4 a1 = *(const float4*)&sA[kk * 132 + ty * 8 + 4];
            ulonglong2 b0 = *(const ulonglong2*)&sB[kk * 128 + tx * 8];
            ulonglong2 b1 = *(const ulonglong2*)&sB[kk * 128 + tx * 8 + 4];
            float ar[8] = {a0.x, a0.y, a0.z, a0.w, a1.x, a1.y, a1.z, a1.w};
#pragma unroll
            for (int r = 0; r < 8; r++) {
                ull av = dup2(ar[r]);
                acc[r][0] = fma2(av, b0.x, acc[r][0]);
                acc[r][1] = fma2(av, b0.y, acc[r][1]);
                acc[r][2] = fma2(av, b1.x, acc[r][2]);
                acc[r][3] = fma2(av, b1.y, acc[r][3]);
            }
        }
        __syncthreads();
    }

    float4 bi0 = *(const float4*)&bias[n0 + tx * 8];
    float4 bi1 = *(const float4*)&bias[n0 + tx * 8 + 4];
#pragma unroll
    for (int r = 0; r < 8; r++) {
        float2 u0 = unpack2(acc[r][0]);
        float2 u1 = unpack2(acc[r][1]);
        float2 u2 = unpack2(acc[r][2]);
        float2 u3 = unpack2(acc[r][3]);
        float4 o0, o1;
        o0.x = u0.x + bi0.x; o0.y = u0.y + bi0.y; o0.z = u1.x + bi0.z; o0.w = u1.y + bi0.w;
        o1.x = u2.x + bi1.x; o1.y = u2.y + bi1.y; o1.z = u3.x + bi1.z; o1.w = u3.y + bi1.w;
        size_t base = (size_t)(m0 + ty * 8 + r) * Hh + n0 + tx * 8;
        *(float4*)&out[base]     = o0;
        *(float4*)&out[base + 4] = o1;
    }
}

// ---------------------------------------------------------------------------
// Fused persistent layer kernel (verified optimum: R12 structure with
// float4 staging at SH_STR=516; mm reads of sH are lane-invariant
// broadcasts so the stride is provably compute-neutral).
// Grid (16 col-tiles of 32 x 8 groups of 32 rows) = 128 CTAs, 256 threads.
// ---------------------------------------------------------------------------
#define SH_STR  516
#define RED_STR 34
#define SWH_F   (512 * NCT)             // 16384 floats
#define SH_F    (32 * SH_STR)           // 16512
#define RED_F   (4 * 32 * RED_STR)      // 4352
#define LAYER_SMEM ((2 * SWH_F + SH_F + RED_F) * 4)   // 214528 B

extern __shared__ float s_mem[];

__global__ __launch_bounds__(256, 1) void layer_kernel(
    const float* __restrict__ xp,  const float* __restrict__ Wh,
    const float* __restrict__ Wx,  const float* __restrict__ bnext,
    float* __restrict__ xpo,       float* __restrict__ hx,
    int* __restrict__ bar, int layer)
{
    float* sWh  = s_mem;                       // [512][32]
    float* sWx  = s_mem + SWH_F;               // [512][32]
    float* sH   = s_mem + 2 * SWH_F;           // [32][516]
    float* sRed = s_mem + 2 * SWH_F + SH_F;    // [4][32][34]

    const int n0 = blockIdx.x * NCT;
    const int b0 = blockIdx.y * 32;
    int* cnt = &bar[layer * 8 + blockIdx.y];

    const int tid  = threadIdx.x;
    const int w    = tid >> 5;
    const int lane = tid & 31;
    const int kc   = w >> 1;             // k-chunk 0..3 (128 k each)
    const int rh   = w & 1;              // row half (16 rows)
    const int rg   = lane >> 3;          // row group of 4 within half
    const int cg   = lane & 7;           // 8 col groups of 4
    const int kbase = kc * 128;
    const int rbase = rh * 16 + rg * 4;

    const int er = tid >> 3;             // epilogue row 0..31
    const int ec = (tid & 7) * 4;        // epilogue col group

    // ---- stage Wh (and Wx_next) column slices once ----
    for (int i = tid; i < 512 * 8; i += 256) {     // 4096 float4 slots
        int k = i >> 3, c4 = i & 7;
        float4 v = *(const float4*)&Wh[(size_t)k * Hh + n0 + c4 * 4];
        *(float4*)&sWh[k * NCT + c4 * 4] = v;
    }
    if (Wx) {
        for (int i = tid; i < 512 * 8; i += 256) {
            int k = i >> 3, c4 = i & 7;
            float4 v = *(const float4*)&Wx[(size_t)k * Hh + n0 + c4 * 4];
            *(float4*)&sWx[k * NCT + c4 * 4] = v;
        }
    }
    float4 bv = make_float4(0.f, 0.f, 0.f, 0.f);
    if (Wx) bv = *(const float4*)&bnext[n0 + ec];

    // ---- t = 0: h0 = tanh(xp0) -> hx[0] ----
    {
        size_t base = ((size_t)(b0 + er) * Tt) * Hh + n0 + ec;
        float4 xv = *(const float4*)&xp[base];
        float4 o;
        o.x = fast_tanh(xv.x); o.y = fast_tanh(xv.y);
        o.z = fast_tanh(xv.z); o.w = fast_tanh(xv.w);
        __stcg((float4*)&hx[(size_t)(b0 + er) * Hh + n0 + ec], o);
    }
    __syncthreads();                 // weights staged + h0 issued
    if (tid == 0) red_release_add(cnt, 1);

    for (int t = 1; t < Tt; t++) {
        // prefetch xp for this step (independent of the flag)
        size_t obase = (((size_t)(b0 + er) * Tt) + t) * Hh + n0 + ec;
        float4 xv = *(const float4*)&xp[obase];

        // ---- wait for all 16 producers of h_{t-1} ----
        if (tid == 0) {
            while (ld_acquire(cnt) < 16 * t) { }
        }
        __syncthreads();

        // ---- stage h_{t-1}[b0..b0+31, :] from hx (float4 STS) ----
        {
            const float* src = hx + ((size_t)((t - 1) & 1)) * (Bb * Hh);
#pragma unroll
            for (int half = 0; half < 2; half++) {
                float4 sv[8];
#pragma unroll
                for (int j = 0; j < 8; j++) {
                    int slot = tid + (half * 8 + j) * 256;
                    int row = slot >> 7, k4 = slot & 127;
                    sv[j] = __ldcg((const float4*)&src[(size_t)(b0 + row) * Hh + k4 * 4]);
                }
#pragma unroll
                for (int j = 0; j < 8; j++) {
                    int slot = tid + (half * 8 + j) * 256;
                    int row = slot >> 7, k4 = slot & 127;
                    *(float4*)&sH[row * SH_STR + k4 * 4] = sv[j];
                }
            }
        }
        __syncthreads();

        // ---- recurrence compute: warp (kc, rh): [16 rows x 32 cols], 128 k ----
        {
            ull a00 = 0, a01 = 0, a10 = 0, a11 = 0,
                a20 = 0, a21 = 0, a30 = 0, a31 = 0;
            const float* hp = &sH[rbase * SH_STR + kbase];
            const float* wp = &sWh[kbase * NCT];
#pragma unroll 8
            for (int kk = 0; kk < 128; kk += 2) {
                float2 h0 = *(const float2*)&hp[kk];
                float2 h1 = *(const float2*)&hp[SH_STR + kk];
                float2 h2 = *(const float2*)&hp[2 * SH_STR + kk];
                float2 h3 = *(const float2*)&hp[3 * SH_STR + kk];
                ulonglong2 wa = *(const ulonglong2*)&wp[kk * NCT + cg * 4];
                ulonglong2 wb = *(const ulonglong2*)&wp[(kk + 1) * NCT + cg * 4];
                ull a;
                a = dup2(h0.x); a00 = fma2(a, wa.x, a00); a01 = fma2(a, wa.y, a01);
                a = dup2(h1.x); a10 = fma2(a, wa.x, a10); a11 = fma2(a, wa.y, a11);
                a = dup2(h2.x); a20 = fma2(a, wa.x, a20); a21 = fma2(a, wa.y, a21);
                a = dup2(h3.x); a30 = fma2(a, wa.x, a30); a31 = fma2(a, wa.y, a31);
                a = dup2(h0.y); a00 = fma2(a, wb.x, a00); a01 = fma2(a, wb.y, a01);
                a = dup2(h1.y); a10 = fma2(a, wb.x, a10); a11 = fma2(a, wb.y, a11);
                a = dup2(h2.y); a20 = fma2(a, wb.x, a20); a21 = fma2(a, wb.y, a21);
                a = dup2(h3.y); a30 = fma2(a, wb.x, a30); a31 = fma2(a, wb.y, a31);
            }
            float* d0 = &sRed[kc * (32 * RED_STR) + (rbase + 0) * RED_STR + cg * 4];
            float* d1 = &sRed[kc * (32 * RED_STR) + (rbase + 1) * RED_STR + cg * 4];
            float* d2 = &sRed[kc * (32 * RED_STR) + (rbase + 2) * RED_STR + cg * 4];
            float* d3 = &sRed[kc * (32 * RED_STR) + (rbase + 3) * RED_STR + cg * 4];
            *(ull*)&d0[0] = a00; *(ull*)&d0[2] = a01;
            *(ull*)&d1[0] = a10; *(ull*)&d1[2] = a11;
            *(ull*)&d2[0] = a20; *(ull*)&d2[2] = a21;
            *(ull*)&d3[0] = a30; *(ull*)&d3[2] = a31;
        }
        __syncthreads();

        // ---- reduce 4 partials, add xp, tanh, store h_t to hx ----
        {
            float2 s0 = make_float2(0.f, 0.f), s1 = make_float2(0.f, 0.f);
            int rb = er * RED_STR + ec;
#pragma unroll
            for (int q = 0; q < 4; q++) {
                float2 u0 = unpack2(*(const ull*)&sRed[q * (32 * RED_STR) + rb]);
                float2 u1 = unpack2(*(const ull*)&sRed[q * (32 * RED_STR) + rb + 2]);
                s0.x += u0.x; s0.y += u0.y; s1.x += u1.x; s1.y += u1.y;
            }
            float4 o;
            o.x = fast_tanh(s0.x + xv.x); o.y = fast_tanh(s0.y + xv.y);
            o.z = fast_tanh(s1.x + xv.z); o.w = fast_tanh(s1.y + xv.w);
            __stcg((float4*)&hx[((size_t)(t & 1)) * (Bb * Hh)
                                + (size_t)(b0 + er) * Hh + n0 + ec], o);
        }
        __syncthreads();                     // sync C: stores issued before release
        if (tid == 0) red_release_add(cnt, 1);

        // ---- FILLER: next layer's projection of h_{t-1} (sH still intact) ----
        if (Wx) {
            ull a00 = 0, a01 = 0, a10 = 0, a11 = 0,
                a20 = 0, a21 = 0, a30 = 0, a31 = 0;
            const float* hp = &sH[rbase * SH_STR + kbase];
            const float* wp = &sWx[kbase * NCT];
#pragma unroll 8
            for (int kk = 0; kk < 128; kk += 2) {
                float2 h0 = *(const float2*)&hp[kk];
                float2 h1 = *(const float2*)&hp[SH_STR + kk];
                float2 h2 = *(const float2*)&hp[2 * SH_STR + kk];
                float2 h3 = *(const float2*)&hp[3 * SH_STR + kk];
                ulonglong2 wa = *(const ulonglong2*)&wp[kk * NCT + cg * 4];
                ulonglong2 wb = *(const ulonglong2*)&wp[(kk + 1) * NCT + cg * 4];
                ull a;
                a = dup2(h0.x); a00 = fma2(a, wa.x, a00); a01 = fma2(a, wa.y, a01);
                a = dup2(h1.x); a10 = fma2(a, wa.x, a10); a11 = fma2(a, wa.y, a11);
                a = dup2(h2.x); a20 = fma2(a, wa.x, a20); a21 = fma2(a, wa.y, a21);
                a = dup2(h3.x); a30 = fma2(a, wa.x, a30); a31 = fma2(a, wa.y, a31);
                a = dup2(h0.y); a00 = fma2(a, wb.x, a00); a01 = fma2(a, wb.y, a01);
                a = dup2(h1.y); a10 = fma2(a, wb.x, a10); a11 = fma2(a, wb.y, a11);
                a = dup2(h2.y); a20 = fma2(a, wb.x, a20); a21 = fma2(a, wb.y, a21);
                a = dup2(h3.y); a30 = fma2(a, wb.x, a30); a31 = fma2(a, wb.y, a31);
            }
            // NOTE: no barrier here — sync C already ordered the recurrence's
            // sRed reads before these writes (provable, not a scheduling guess).
            float* d0 = &sRed[kc * (32 * RED_STR) + (rbase + 0) * RED_STR + cg * 4];
            float* d1 = &sRed[kc * (32 * RED_STR) + (rbase + 1) * RED_STR + cg * 4];
            float* d2 = &sRed[kc * (32 * RED_STR) + (rbase + 2) * RED_STR + cg * 4];
            float* d3 = &sRed[kc * (32 * RED_STR) + (rbase + 3) * RED_STR + cg * 4];
            *(ull*)&d0[0] = a00; *(ull*)&d0[2] = a01;
            *(ull*)&d1[0] = a10; *(ull*)&d1[2] = a11;
            *(ull*)&d2[0] = a20; *(ull*)&d2[2] = a21;
            *(ull*)&d3[0] = a30; *(ull*)&d3[2] = a31;
            __syncthreads();
            float2 s0 = make_float2(0.f, 0.f), s1 = make_float2(0.f, 0.f);
            int rb = er * RED_STR + ec;
#pragma unroll
            for (int q = 0; q < 4; q++) {
                float2 u0 = unpack2(*(const ull*)&sRed[q * (32 * RED_STR) + rb]);
                float2 u1 = unpack2(*(const ull*)&sRed[q * (32 * RED_STR) + rb + 2]);
                s0.x += u0.x; s0.y += u0.y; s1.x += u1.x; s1.y += u1.y;
            }
            float4 o;
            o.x = s0.x + bv.x; o.y = s0.y + bv.y;
            o.z = s1.x + bv.z; o.w = s1.y + bv.w;
            *(float4*)&xpo[(((size_t)(b0 + er) * Tt) + (t - 1)) * Hh + n0 + ec] = o;
        }
    }

    // ---- tail: projection of h_{Tt-1} ----
    if (Wx) {
        if (tid == 0) {
            while (ld_acquire(cnt) < 16 * Tt) { }
        }
        __syncthreads();
        {
            const float* src = hx + ((size_t)((Tt - 1) & 1)) * (Bb * Hh);
#pragma unroll
            for (int half = 0; half < 2; half++) {
                float4 sv[8];
#pragma unroll
                for (int j = 0; j < 8; j++) {
                    int slot = tid + (half * 8 + j) * 256;
                    int row = slot >> 7, k4 = slot & 127;
                    sv[j] = __ldcg((const float4*)&src[(size_t)(b0 + row) * Hh + k4 * 4]);
                }
#pragma unroll
                for (int j = 0; j < 8; j++) {
                    int slot = tid + (half * 8 + j) * 256;
                    int row = slot >> 7, k4 = slot & 127;
                    *(float4*)&sH[row * SH_STR + k4 * 4] = sv[j];
                }
            }
        }
        __syncthreads();
        {
            ull a00 = 0, a01 = 0, a10 = 0, a11 = 0,
                a20 = 0, a21 = 0, a30 = 0, a31 = 0;
            const float* hp = &sH[rbase * SH_STR + kbase];
            const float* wp = &sWx[kbase * NCT];
#pragma unroll 8
            for (int kk = 0; kk < 128; kk += 2) {
                float2 h0 = *(const float2*)&hp[kk];
                float2 h1 = *(const float2*)&hp[SH_STR + kk];
                float2 h2 = *(const float2*)&hp[2 * SH_STR + kk];
                float2 h3 = *(const float2*)&hp[3 * SH_STR + kk];
                ulonglong2 wa = *(const ulonglong2*)&wp[kk * NCT + cg * 4];
                ulonglong2 wb = *(const ulonglong2*)&wp[(kk + 1) * NCT + cg * 4];
                ull a;
                a = dup2(h0.x); a00 = fma2(a, wa.x, a00); a01 = fma2(a, wa.y, a01);
                a = dup2(h1.x); a10 = fma2(a, wa.x, a10); a11 = fma2(a, wa.y, a11);
                a = dup2(h2.x); a20 = fma2(a, wa.x, a20); a21 = fma2(a, wa.y, a21);
                a = dup2(h3.x); a30 = fma2(a, wa.x, a30); a31 = fma2(a, wa.y, a31);
                a = dup2(h0.y); a00 = fma2(a, wb.x, a00); a01 = fma2(a, wb.y, a01);
                a = dup2(h1.y); a10 = fma2(a, wb.x, a10); a11 = fma2(a, wb.y, a11);
                a = dup2(h2.y); a20 = fma2(a, wb.x, a20); a21 = fma2(a, wb.y, a21);
                a = dup2(h3.y); a30 = fma2(a, wb.x, a30); a31 = fma2(a, wb.y, a31);
            }
            float* d0 = &sRed[kc * (32 * RED_STR) + (rbase + 0) * RED_STR + cg * 4];
            float* d1 = &sRed[kc * (32 * RED_STR) + (rbase + 1) * RED_STR + cg * 4];
            float* d2 = &sRed[kc * (32 * RED_STR) + (rbase + 2) * RED_STR + cg * 4];
            float* d3 = &sRed[kc * (32 * RED_STR) + (rbase + 3) * RED_STR + cg * 4];
            *(ull*)&d0[0] = a00; *(ull*)&d0[2] = a01;
            *(ull*)&d1[0] = a10; *(ull*)&d1[2] = a11;
            *(ull*)&d2[0] = a20; *(ull*)&d2[2] = a21;
            *(ull*)&d3[0] = a30; *(ull*)&d3[2] = a31;
            __syncthreads();
            float2 s0 = make_float2(0.f, 0.f), s1 = make_float2(0.f, 0.f);
            int rb = er * RED_STR + ec;
#pragma unroll
            for (int q = 0; q < 4; q++) {
                float2 u0 = unpack2(*(const ull*)&sRed[q * (32 * RED_STR) + rb]);
                float2 u1 = unpack2(*(const ull*)&sRed[q * (32 * RED_STR) + rb + 2]);
                s0.x += u0.x; s0.y += u0.y; s1.x += u1.x; s1.y += u1.y;
            }
            float4 o;
            o.x = s0.x + bv.x; o.y = s0.y + bv.y;
            o.z = s1.x + bv.z; o.w = s1.y + bv.w;
            *(float4*)&xpo[(((size_t)(b0 + er) * Tt) + (Tt - 1)) * Hh + n0 + ec] = o;
        }
    }
}

// ---------------------------------------------------------------------------
// Final: out[b] = hx[1][b,:] @ Wf + bf   (h at t=255, parity 1)
// ---------------------------------------------------------------------------
__global__ void final_kernel(const float* __restrict__ hx, const float* __restrict__ Wf,
                             const float* __restrict__ bf, float* __restrict__ out)
{
    int b = blockIdx.x;
    const float* row = hx + (size_t)(Bb * Hh) + (size_t)b * Hh;
    float s = 0.f;
    for (int j = threadIdx.x; j < Hh; j += 128) s += row[j] * Wf[j];
#pragma unroll
    for (int o = 16; o > 0; o >>= 1) s += __shfl_down_sync(0xffffffffu, s, o);
    __shared__ float ws[4];
    if ((threadIdx.x & 31) == 0) ws[threadIdx.x >> 5] = s;
    __syncthreads();
    if (threadIdx.x == 0) out[b] = ws[0] + ws[1] + ws[2] + ws[3] + bf[0];
}

// ---------------------------------------------------------------------------
extern "C" void kernel_launch(void* const* d_in, const int* in_sizes, int n_in,
                              void* d_out, int out_size)
{
    const float* x    = (const float*)d_in[0];
    const float* Wx0  = (const float*)d_in[1];
    const float* Wh0  = (const float*)d_in[2];
    const float* bi0  = (const float*)d_in[3];
    const float* Wx1  = (const float*)d_in[4];
    const float* Wh1  = (const float*)d_in[5];
    const float* bi1  = (const float*)d_in[6];
    const float* Wx2  = (const float*)d_in[7];
    const float* Wh2  = (const float*)d_in[8];
    const float* bi2  = (const float*)d_in[9];
    const float* Wf   = (const float*)d_in[10];
    const float* bf   = (const float*)d_in[11];
    float* out = (float*)d_out;

    void* p;
    cudaGetSymbolAddress(&p, g_xp);
    float* xpA = (float*)p;
    cudaGetSymbolAddress(&p, g_xq);
    float* xpB = (float*)p;
    cudaGetSymbolAddress(&p, g_hx);
    float* hx = (float*)p;
    cudaGetSymbolAddress(&p, g_bar);
    int* bar = (int*)p;

    cudaFuncSetAttribute(layer_kernel, cudaFuncAttributeMaxDynamicSharedMemorySize, LAYER_SMEM);

    dim3 pgrid(Hh / 128, (Bb * Tt) / 128);   // (4, 512)
    dim3 lgrid(Hh / NCT, Bb / 32);           // (16, 8) = 128 CTAs

    // layer 0 input projection (K=64); block (0,0) zeroes the counters
    proj_kernel<Dd><<<pgrid, 256>>>(x, Wx0, bi0, xpA);
    // layer 0 recurrence + fused projection for layer 1
    layer_kernel<<<lgrid, 256, LAYER_SMEM>>>(xpA, Wh0, Wx1, bi1, xpB, hx, bar, 0);
    // layer 1 recurrence + fused projection for layer 2
    layer_kernel<<<lgrid, 256, LAYER_SMEM>>>(xpB, Wh1, Wx2, bi2, xpA, hx, bar, 1);
    // layer 2 recurrence only
    layer_kernel<<<lgrid, 256, LAYER_SMEM>>>(xpA, Wh2, nullptr, nullptr, nullptr, hx, bar, 2);
    // head
    final_kernel<<<Bb, 128>>>(hx, Wf, bf, out);
}